// round 9
// baseline (speedup 1.0000x reference)
#include <cuda_runtime.h>
#include <cuda_fp16.h>
#include <math.h>
#include <cstdint>

// Problem constants
#define BSZ    2
#define CDIM   256
#define NDIM   16384      // 128*128
#define HDIM   128
#define WDIM   128
#define NKV    1024       // 32*32
#define NHEADS 8
#define HD     32
#define EPSBN  1e-5f
#define KSR    4096       // CDIM*4*4

typedef unsigned long long u64;
typedef unsigned int u32;
typedef unsigned short u16;

// ===================== f32x2 helpers (scalar k GEMM) ==========================
__device__ __forceinline__ u64 pack2(float lo, float hi) {
    u64 r; asm("mov.b64 %0, {%1, %2};" : "=l"(r) : "f"(lo), "f"(hi)); return r;
}
__device__ __forceinline__ u64 fma2(u64 a, u64 b, u64 c) {
    u64 d; asm("fma.rn.f32x2 %0, %1, %2, %3;" : "=l"(d) : "l"(a), "l"(b), "l"(c)); return d;
}
__device__ __forceinline__ float2 unpack2(u64 a) {
    float lo, hi; asm("mov.b64 {%0, %1}, %2;" : "=f"(lo), "=f"(hi) : "l"(a));
    return make_float2(lo, hi);
}

// ===================== mma/ldmatrix helpers (fp16) ============================
__device__ __forceinline__ u32 smem_u32(const void* p) {
    u32 a; asm("{ .reg .u64 t; cvta.to.shared.u64 t, %1; cvt.u32.u64 %0, t; }"
               : "=r"(a) : "l"(p)); return a;
}
__device__ __forceinline__ void ldm_x4(u32 r[4], u32 addr) {
    asm volatile("ldmatrix.sync.aligned.m8n8.x4.shared.b16 {%0,%1,%2,%3}, [%4];"
                 : "=r"(r[0]), "=r"(r[1]), "=r"(r[2]), "=r"(r[3]) : "r"(addr));
}
__device__ __forceinline__ void mma_z(float& c0, float& c1, float& c2, float& c3,
                                      u32 a0, u32 a1, u32 a2, u32 a3,
                                      u32 b0, u32 b1) {
    asm volatile("mma.sync.aligned.m16n8k16.row.col.f32.f16.f16.f32 "
                 "{%0,%1,%2,%3}, {%4,%5,%6,%7}, {%8,%9}, {%10,%10,%10,%10};"
                 : "=f"(c0), "=f"(c1), "=f"(c2), "=f"(c3)
                 : "r"(a0), "r"(a1), "r"(a2), "r"(a3), "r"(b0), "r"(b1), "f"(0.0f));
}
__device__ __forceinline__ void mma_a(float& c0, float& c1, float& c2, float& c3,
                                      u32 a0, u32 a1, u32 a2, u32 a3,
                                      u32 b0, u32 b1) {
    asm volatile("mma.sync.aligned.m16n8k16.row.col.f32.f16.f16.f32 "
                 "{%0,%1,%2,%3}, {%4,%5,%6,%7}, {%8,%9}, {%0,%1,%2,%3};"
                 : "+f"(c0), "+f"(c1), "+f"(c2), "+f"(c3)
                 : "r"(a0), "r"(a1), "r"(a2), "r"(a3), "r"(b0), "r"(b1));
}
__device__ __forceinline__ u32 sw128(u32 b) { return b ^ ((b >> 3) & 0x70); }

// ===================== fp16 pack helpers ======================================
__device__ __forceinline__ u32 cvt2h(float a, float b) {
    __half2 h = __floats2half2_rn(a, b);
    return *reinterpret_cast<u32*>(&h);
}
__device__ __forceinline__ u64 cvt4h(float4 v) {
    u32 lo = cvt2h(v.x, v.y), hi = cvt2h(v.z, v.w);
    return (u64)lo | ((u64)hi << 32);
}

// ===================== scratch ================================================
__device__ __align__(16) u16  g_qbf [BSZ * NHEADS * NDIM * 32];  // fp16, 64B rows
__device__ __align__(16) u16  g_kbf [BSZ * NHEADS * NKV  * 32];  // fp16, 64B rows
__device__ __align__(16) u16  g_Xt  [BSZ * NDIM * 256];          // fp16 single
__device__ __align__(16) u16  g_Xp  [BSZ * NKV * 4096];          // fp16 single
__device__ __align__(16) u16  g_wqs [CDIM * 256];                // fp16 single
__device__ __align__(16) u16  g_wsrs[CDIM * 4096];               // fp16 single
__device__ float g_part[16 * CDIM * NKV];
__device__ float g_xr  [BSZ * CDIM * NKV];
__device__ float g_attn[2 * BSZ * NHEADS * NDIM];                // [half][bh][n]
__device__ float g_S   [BSZ * NDIM];
__device__ float g_vp  [BSZ * CDIM * 256];
__device__ float g_v   [BSZ * CDIM];
__device__ float g_alpha[BSZ * CDIM];
__device__ float g_bias [CDIM];

// ===================== prep: W fp32 -> fp16 rows ==============================
__global__ __launch_bounds__(256) void convert_w(
    const float* __restrict__ W, u16* __restrict__ out) {
    const int idx = blockIdx.x * 256 + threadIdx.x;
    const int fl = idx * 4;
    float4 v = *(const float4*)&W[fl];
    *(u64*)(out + fl) = cvt4h(v);
}

// ===================== prep: x -> Xt (tile transpose -> fp16) + v partials ====
__global__ __launch_bounds__(256) void transpose_split_x(
    const float* __restrict__ x, u16* __restrict__ Xt, float* __restrict__ vp) {
    __shared__ float s[64][65];
    const int n0 = blockIdx.x * 64;
    const int c0 = blockIdx.y * 64;
    const int b  = blockIdx.z;
    const int tid = threadIdx.x;
    #pragma unroll
    for (int i = 0; i < 4; ++i) {
        const int idx = i * 256 + tid;
        const int c_l = idx >> 4, nq = idx & 15;
        float4 v = *(const float4*)&x[((size_t)(b * CDIM + c0 + c_l)) * NDIM + n0 + nq * 4];
        s[c_l][nq * 4 + 0] = v.x; s[c_l][nq * 4 + 1] = v.y;
        s[c_l][nq * 4 + 2] = v.z; s[c_l][nq * 4 + 3] = v.w;
    }
    __syncthreads();
    const int n_l = tid >> 2, cq = tid & 3;
    u16* orow = Xt + ((size_t)(b * NDIM + n0 + n_l)) * 256 + c0;
    #pragma unroll
    for (int i = 0; i < 4; ++i) {
        const int c_loc = (cq + i * 4) * 4;
        float4 v = make_float4(s[c_loc][n_l], s[c_loc + 1][n_l],
                               s[c_loc + 2][n_l], s[c_loc + 3][n_l]);
        *(u64*)(orow + c_loc) = cvt4h(v);
    }
    if (tid < 64) {
        float acc = 0.f;
        #pragma unroll 16
        for (int n = 0; n < 64; ++n) acc += s[tid][n];
        vp[((size_t)(b * CDIM + c0 + tid)) * 256 + blockIdx.x] = acc;
    }
}

// ---------------- v = mean (reduce partials) ----------------------------------
__global__ __launch_bounds__(256) void vp_reduce(const float* __restrict__ vp,
                                                 float* __restrict__ v) {
    const int bc = blockIdx.x;
    __shared__ float red[256];
    red[threadIdx.x] = vp[(size_t)bc * 256 + threadIdx.x];
    __syncthreads();
    for (int st = 128; st > 0; st >>= 1) {
        if (threadIdx.x < st) red[threadIdx.x] += red[threadIdx.x + st];
        __syncthreads();
    }
    if (threadIdx.x == 0) v[bc] = red[0] * (1.0f / NDIM);
}

// ===================== prep: x -> Xp (patch gather -> fp16) ===================
__global__ __launch_bounds__(256) void gather_patches(
    const float* __restrict__ x, u16* __restrict__ Xp) {
    extern __shared__ char gsm[];   // 32KB
    const int cch = blockIdx.x;
    const int hh  = blockIdx.y;
    const int b   = blockIdx.z;
    const int tid = threadIdx.x;
    #pragma unroll
    for (int i = 0; i < 16; ++i) {
        const int idx = i * 256 + tid;
        const int c_l = idx >> 7;
        const int rem = idx & 127;
        const int p = rem >> 5, w4 = rem & 31;
        float4 v = *(const float4*)&x[((size_t)(b * CDIM + cch * 32 + c_l)) * NDIM
                                      + (hh * 4 + p) * WDIM + w4 * 4];
        const u32 off = (u32)(c_l * 32 + p * 8);
        const u32 phys = (off ^ ((u32)(w4 & 15) << 3)) + (u32)w4 * 1024;
        *(u64*)(gsm + phys) = cvt4h(v);
    }
    __syncthreads();
    #pragma unroll
    for (int i = 0; i < 16; ++i) {
        const int idx = i * 256 + tid;
        const int ww = idx >> 7, j = idx & 127;
        const u32 phys = (((u32)j * 8) ^ ((u32)(ww & 15) << 3)) + (u32)ww * 1024;
        u16* dst = Xp + ((size_t)(b * NKV + hh * 32 + ww)) * 4096 + cch * 512 + j * 4;
        *(u64*)dst = *(const u64*)(gsm + phys);
    }
}

// ===================== q GEMM on mma.sync (X single, W single) ================
__global__ __launch_bounds__(256, 2) void qgemm_mma(
    const u16* __restrict__ Xt, const u16* __restrict__ Wq,
    u16* __restrict__ qbf) {
    extern __shared__ char sm[];
    const u32 sb = smem_u32(sm);
    const int tid = threadIdx.x;
    const int l = tid & 31, wid = tid >> 5;
    const int wm = wid & 3, wo = wid >> 2;
    const int blkn = blockIdx.x, blko = blockIdx.y, bb = blockIdx.z;

    const u16* XtB = Xt + (size_t)(bb * NDIM + blkn * 128) * 256;
    const u16* WqB = Wq + (size_t)(blko * 128) * 256;

    float acc[2][8][4];
    #pragma unroll
    for (int a = 0; a < 2; ++a)
        #pragma unroll
        for (int c = 0; c < 8; ++c)
            #pragma unroll
            for (int d = 0; d < 4; ++d) acc[a][c][d] = 0.f;

    u32 rowA[2], rowB[4];
    #pragma unroll
    for (int mt = 0; mt < 2; ++mt)
        rowA[mt] = (u32)(wm * 32 + mt * 16 + (l & 7) + (l & 8)) * 128;
    #pragma unroll
    for (int g = 0; g < 4; ++g)
        rowB[g] = (u32)(wo * 64 + g * 16 + (l & 7) + ((l & 16) >> 1)) * 128;

    for (int kc = 0; kc < 4; ++kc) {
        for (int i = tid; i < 1024; i += 256) {
            const int row = i >> 3, ch = i & 7;
            const u32 dst = sw128((u32)(row * 128 + ch * 16));
            const size_t off = (size_t)row * 256 + kc * 64 + ch * 8;
            *(uint4*)(sm + dst)         = *(const uint4*)(XtB + off);
            *(uint4*)(sm + 16384 + dst) = *(const uint4*)(WqB + off);
        }
        __syncthreads();
        #pragma unroll
        for (int s = 0; s < 4; ++s) {
            const u32 cA = ((u32)((2 * s + ((l >> 4) & 1)) ^ (l & 7))) << 4;
            const u32 cB = ((u32)((2 * s + ((l >> 3) & 1)) ^ (l & 7))) << 4;
            u32 a[2][4], bf[4][4];
            #pragma unroll
            for (int mt = 0; mt < 2; ++mt)
                ldm_x4(a[mt], sb + rowA[mt] + cA);
            #pragma unroll
            for (int g = 0; g < 4; ++g)
                ldm_x4(bf[g], sb + 16384 + rowB[g] + cB);
            #pragma unroll
            for (int mt = 0; mt < 2; ++mt)
                #pragma unroll
                for (int g = 0; g < 4; ++g)
                    #pragma unroll
                    for (int hf = 0; hf < 2; ++hf) {
                        float* A4 = acc[mt][g * 2 + hf];
                        mma_a(A4[0], A4[1], A4[2], A4[3],
                              a[mt][0], a[mt][1], a[mt][2], a[mt][3],
                              bf[g][2 * hf], bf[g][2 * hf + 1]);
                    }
        }
        __syncthreads();
    }

    // epilogue: single fp16 q rows (32 fp16 = 64B)
    #pragma unroll
    for (int mt = 0; mt < 2; ++mt) {
        const int n0g = blkn * 128 + wm * 32 + mt * 16 + (l >> 2);
        #pragma unroll
        for (int nt = 0; nt < 8; ++nt) {
            const int o = blko * 128 + wo * 64 + nt * 8 + 2 * (l & 3);
            const int bh_ = bb * NHEADS + (o >> 5);
            const int d = o & 31;
            u16* base = qbf + ((size_t)bh_ * NDIM + n0g) * 32 + d;
            *(u32*)base = cvt2h(acc[mt][nt][0], acc[mt][nt][1]);
            *(u32*)(base + 8 * 32) = cvt2h(acc[mt][nt][2], acc[mt][nt][3]);
        }
    }
}

// ===================== conv GEMM on mma.sync (single fp16, split-K=8) =========
__global__ __launch_bounds__(256, 2) void convgemm_mma(
    const u16* __restrict__ Wsr, const u16* __restrict__ Xp,
    float* __restrict__ part) {
    extern __shared__ char sm[];
    const u32 sb = smem_u32(sm);
    const int tid = threadIdx.x;
    const int l = tid & 31, wid = tid >> 5;
    const int wm = wid & 3, wo = wid >> 2;
    const int blkm = blockIdx.x, blko = blockIdx.y;
    const int zz = blockIdx.z;
    const int bb = zz & 1, ks = zz >> 1;

    const u16* AB = Wsr + (size_t)(blko * 128) * 4096;
    const u16* BB = Xp + (size_t)(bb * NKV + blkm * 128) * 4096;

    float acc[2][8][4];
    #pragma unroll
    for (int a = 0; a < 2; ++a)
        #pragma unroll
        for (int c = 0; c < 8; ++c)
            #pragma unroll
            for (int d = 0; d < 4; ++d) acc[a][c][d] = 0.f;

    u32 rowA[2], rowB[4];
    #pragma unroll
    for (int mt = 0; mt < 2; ++mt)
        rowA[mt] = (u32)(wm * 32 + mt * 16 + (l & 7) + (l & 8)) * 128;
    #pragma unroll
    for (int g = 0; g < 4; ++g)
        rowB[g] = (u32)(wo * 64 + g * 16 + (l & 7) + ((l & 16) >> 1)) * 128;

    for (int kcl = 0; kcl < 8; ++kcl) {
        const int kcg = ks * 8 + kcl;
        for (int i = tid; i < 1024; i += 256) {
            const int row = i >> 3, ch = i & 7;
            const u32 dst = sw128((u32)(row * 128 + ch * 16));
            const size_t off = (size_t)row * 4096 + kcg * 64 + ch * 8;
            *(uint4*)(sm + dst)         = *(const uint4*)(AB + off);
            *(uint4*)(sm + 16384 + dst) = *(const uint4*)(BB + off);
        }
        __syncthreads();
        #pragma unroll
        for (int s = 0; s < 4; ++s) {
            const u32 cA = ((u32)((2 * s + ((l >> 4) & 1)) ^ (l & 7))) << 4;
            const u32 cB = ((u32)((2 * s + ((l >> 3) & 1)) ^ (l & 7))) << 4;
            u32 a[2][4], bf[4][4];
            #pragma unroll
            for (int mt = 0; mt < 2; ++mt)
                ldm_x4(a[mt], sb + rowA[mt] + cA);
            #pragma unroll
            for (int g = 0; g < 4; ++g)
                ldm_x4(bf[g], sb + 16384 + rowB[g] + cB);
            #pragma unroll
            for (int mt = 0; mt < 2; ++mt)
                #pragma unroll
                for (int g = 0; g < 4; ++g)
                    #pragma unroll
                    for (int hf = 0; hf < 2; ++hf) {
                        float* A4 = acc[mt][g * 2 + hf];
                        mma_a(A4[0], A4[1], A4[2], A4[3],
                              a[mt][0], a[mt][1], a[mt][2], a[mt][3],
                              bf[g][2 * hf], bf[g][2 * hf + 1]);
                    }
        }
        __syncthreads();
    }

    #pragma unroll
    for (int mt = 0; mt < 2; ++mt) {
        const int o = blko * 128 + wm * 32 + mt * 16 + (l >> 2);
        #pragma unroll
        for (int nt = 0; nt < 8; ++nt) {
            const int m = blkm * 128 + wo * 64 + nt * 8 + 2 * (l & 3);
            float* dst = part + ((size_t)zz * CDIM + o) * NKV + m;
            *(float2*)dst = make_float2(acc[mt][nt][0], acc[mt][nt][1]);
            *(float2*)(dst + 8 * NKV) = make_float2(acc[mt][nt][2], acc[mt][nt][3]);
        }
    }
}

// ===================== conv reduce + BN =======================================
__global__ __launch_bounds__(256) void conv_reduce_bn(
    const float* __restrict__ part,
    const float* __restrict__ gam, const float* __restrict__ bet,
    const float* __restrict__ mu,  const float* __restrict__ var,
    float* __restrict__ xr) {
    const int idx = blockIdx.x * 256 + threadIdx.x;
    const int fl = idx * 4;
    const int b = fl >> 18;
    const int o = (fl >> 10) & 255;
    const int m = fl & 1023;
    float4 s = make_float4(0.f, 0.f, 0.f, 0.f);
    #pragma unroll
    for (int ks = 0; ks < 8; ++ks) {
        const float4 p = *(const float4*)&part[((size_t)(ks * 2 + b) * CDIM + o) * NKV + m];
        s.x += p.x; s.y += p.y; s.z += p.z; s.w += p.w;
    }
    const float inv = gam[o] * rsqrtf(var[o] + EPSBN);
    const float mb = mu[o], be = bet[o];
    float4 r = make_float4((s.x - mb) * inv + be, (s.y - mb) * inv + be,
                           (s.z - mb) * inv + be, (s.w - mb) * inv + be);
    *(float4*)&xr[((size_t)(b * CDIM + o)) * NKV + m] = r;
}

// ===================== k GEMM (scalar f32x2, fp16 epilogue) ===================
__global__ __launch_bounds__(256) void gemm_split(
    const float* __restrict__ W, const float* __restrict__ X,
    u16* __restrict__ Out, int Ncol) {
    __shared__ float As[16][64];
    __shared__ float Bs[16][64];
    const int b  = blockIdx.z;
    const float* Xb = X + (size_t)b * CDIM * Ncol;
    const int bm = blockIdx.y * 64;
    const int bn = blockIdx.x * 64;
    const int tid = threadIdx.x;
    const int tm = tid >> 4, tn = tid & 15;

    u64 acc[4][2] = {};
    for (int k0 = 0; k0 < CDIM; k0 += 16) {
        const int ar = tid >> 2, ac = (tid & 3) * 4;
        float4 a4 = *(const float4*)&W[(size_t)(bm + ar) * CDIM + k0 + ac];
        As[ac + 0][ar] = a4.x; As[ac + 1][ar] = a4.y;
        As[ac + 2][ar] = a4.z; As[ac + 3][ar] = a4.w;
        const int br = tid >> 4, bc = (tid & 15) * 4;
        *(float4*)&Bs[br][bc] = *(const float4*)&Xb[(size_t)(k0 + br) * Ncol + bn + bc];
        __syncthreads();
        #pragma unroll
        for (int kk = 0; kk < 16; ++kk) {
            float4 av = *(const float4*)&As[kk][tm * 4];
            ulonglong2 bv = *(const ulonglong2*)&Bs[kk][tn * 4];
            u64 a0 = pack2(av.x, av.x), a1 = pack2(av.y, av.y);
            u64 a2 = pack2(av.z, av.z), a3 = pack2(av.w, av.w);
            acc[0][0] = fma2(a0, bv.x, acc[0][0]); acc[0][1] = fma2(a0, bv.y, acc[0][1]);
            acc[1][0] = fma2(a1, bv.x, acc[1][0]); acc[1][1] = fma2(a1, bv.y, acc[1][1]);
            acc[2][0] = fma2(a2, bv.x, acc[2][0]); acc[2][1] = fma2(a2, bv.y, acc[2][1]);
            acc[3][0] = fma2(a3, bv.x, acc[3][0]); acc[3][1] = fma2(a3, bv.y, acc[3][1]);
        }
        __syncthreads();
    }
    const int o0 = bm + tm * 4;        // 4 consecutive o (same head), multiple of 4
    const int d0 = o0 & 31;
    const int bh = b * NHEADS + (o0 >> 5);
    #pragma unroll
    for (int j = 0; j < 4; ++j) {
        const int col = bn + tn * 4 + j;
        float vs[4];
        #pragma unroll
        for (int i = 0; i < 4; ++i) {
            float2 f = unpack2(acc[i][j >> 1]);
            vs[i] = (j & 1) ? f.y : f.x;
        }
        u16* base = Out + ((size_t)bh * Ncol + col) * 32 + d0;
        *(u64*)base = cvt4h(make_float4(vs[0], vs[1], vs[2], vs[3]));
    }
}

// ---------------- alpha/bias --------------------------------------------------
__global__ __launch_bounds__(256) void alpha_kernel(
    const float* __restrict__ wproj, const float* __restrict__ v,
    const float* __restrict__ gam, const float* __restrict__ bet,
    const float* __restrict__ mu,  const float* __restrict__ var,
    float* __restrict__ alpha, float* __restrict__ bias) {
    const int b = blockIdx.x;
    const int o = threadIdx.x;
    __shared__ float vs[CDIM];
    vs[o] = v[b * CDIM + o];
    __syncthreads();
    float p = 0.f;
    const float* wr = wproj + (size_t)o * CDIM;
    #pragma unroll 8
    for (int c = 0; c < CDIM; ++c) p = fmaf(wr[c], vs[c], p);
    const float inv = gam[o] * rsqrtf(var[o] + EPSBN);
    alpha[b * CDIM + o] = p * inv;
    if (b == 0) bias[o] = bet[o] - mu[o] * inv;
}

// ===================== fp16 mma.sync attention (kv-split) =====================
// grid (seg 8, half 2, bh 16); 256 threads; smem = k 32KB + q 8KB = 40KB.
#define SM_QOFF 32768
#define SM_TOT  40960
#define NTILES  16

__global__ __launch_bounds__(256, 2)
void attn_mma(const u16* __restrict__ qbf, const u16* __restrict__ kbf,
              float* __restrict__ attn) {
    extern __shared__ char smem[];
    const u32 sb  = smem_u32(smem);
    const int tid = threadIdx.x;
    const int wid = tid >> 5, l = tid & 31;
    const int seg  = blockIdx.x;
    const int half = blockIdx.y;
    const int bh   = blockIdx.z;

    // stage this half's k (512 rows x 64B)
    {
        const uint4* ksrc = (const uint4*)(kbf + (size_t)(bh * NKV + half * 512) * 32);
        for (int idx = tid; idx < 512 * 4; idx += 256) {
            const int row = idx >> 2, c = idx & 3;
            const u32 off = (u32)((row >> 1) * 128 + (row & 1) * 64 + c * 16);
            *(uint4*)(smem + sw128(off)) = ksrc[idx];
        }
    }
    __syncthreads();

    const int brow = (l & 7) + ((l & 16) >> 1);
    u32 baddr[2];
    #pragma unroll
    for (int s = 0; s < 2; ++s) {
        const u32 off = (u32)((brow >> 1) * 128 + (brow & 1) * 64
                              + (2 * s + ((l >> 3) & 1)) * 16);
        baddr[s] = sb + sw128(off);
    }
    const int Rr = wid * 16 + (l & 15);
    u32 aaddr[2];
    #pragma unroll
    for (int s = 0; s < 2; ++s) {
        const u32 off = (u32)((Rr >> 1) * 128 + (Rr & 1) * 64 + (2 * s + (l >> 4)) * 16);
        aaddr[s] = sb + SM_QOFF + sw128(off);
    }

    const float scale = 0.17677669529663687f;
    float* ob = attn + ((size_t)(half * 16 + bh)) * NDIM;

    for (int t = 0; t < NTILES; ++t) {
        const int n_base = (seg * NTILES + t) * 128;
        {
            const uint4* qsrc = (const uint4*)(qbf + ((size_t)bh * NDIM + n_base) * 32);
            const int row = tid >> 1;
            const int c0 = (tid & 1) * 2;
            #pragma unroll
            for (int j = 0; j < 2; ++j) {
                const int c = c0 + j;
                const u32 off = (u32)((row >> 1) * 128 + (row & 1) * 64 + c * 16);
                *(uint4*)(smem + SM_QOFF + sw128(off)) = qsrc[(size_t)row * 4 + c];
            }
        }
        __syncwarp();

        u32 a[2][4];
        ldm_x4(a[0], aaddr[0]);
        ldm_x4(a[1], aaddr[1]);
        __syncwarp();

        float rmax[2] = {-INFINITY, -INFINITY};
        for (int kv = 0; kv < 32; ++kv) {
            const u32 off = (u32)kv * 1024;
            u32 b0[4], b1[4];
            ldm_x4(b0, baddr[0] + off);
            ldm_x4(b1, baddr[1] + off);
            #pragma unroll
            for (int g = 0; g < 2; ++g) {
                float A0, A1, A2, A3, B0, B1, B2, B3;
                mma_z(A0, A1, A2, A3, a[0][0], a[0][1], a[0][2], a[0][3],
                      b0[2 * g], b0[2 * g + 1]);
                mma_z(B0, B1, B2, B3, a[1][0], a[1][1], a[1][2], a[1][3],
                      b1[2 * g], b1[2 * g + 1]);
                rmax[0] = fmaxf(rmax[0], fmaxf(A0 + B0, A1 + B1));
                rmax[1] = fmaxf(rmax[1], fmaxf(A2 + B2, A3 + B3));
            }
        }
        #pragma unroll
        for (int rr = 0; rr < 2; ++rr) {
            float v = rmax[rr];
            v = fmaxf(v, __shfl_xor_sync(0xffffffffu, v, 1));
            v = fmaxf(v, __shfl_xor_sync(0xffffffffu, v, 2));
            rmax[rr] = v;
        }
        if ((l & 3) == 0) {
            const int rbase = n_base + wid * 16;
            ob[rbase + (l >> 2) + 0] = rmax[0] * scale;
            ob[rbase + (l >> 2) + 8] = rmax[1] * scale;
        }
        __syncwarp();
    }
}

// ---------------- S[b][n] = sum_h max(half0, half1) ---------------------------
__global__ __launch_bounds__(256) void reduce_attn(const float* __restrict__ attn,
                                                   float* __restrict__ S) {
    const int idx = blockIdx.x * 256 + threadIdx.x;
    const int b = idx >> 14, n = idx & (NDIM - 1);
    float s = 0.f;
    #pragma unroll
    for (int h = 0; h < NHEADS; ++h) {
        const size_t base = ((size_t)(b * NHEADS + h)) * NDIM + n;
        s += fmaxf(attn[base], attn[base + (size_t)16 * NDIM]);
    }
    S[idx] = s;
}

// ---------------- out = alpha*S + bias -----------------------------------------
__global__ __launch_bounds__(256) void final_kernel(
    const float* __restrict__ S, const float* __restrict__ alpha,
    const float* __restrict__ bias, float* __restrict__ out) {
    const size_t t = (size_t)blockIdx.x * 256 + threadIdx.x;
    const size_t idx4 = t * 4;
    const int bo = (int)(idx4 >> 14);
    const int n  = (int)(idx4 & (NDIM - 1));
    const int b  = bo >> 8, o = bo & 255;
    const float a  = alpha[bo];
    const float bi = bias[o];
    float4 s = *(const float4*)&S[(size_t)b * NDIM + n];
    float4 r;
    r.x = fmaf(a, s.x, bi); r.y = fmaf(a, s.y, bi);
    r.z = fmaf(a, s.z, bi); r.w = fmaf(a, s.w, bi);
    *(float4*)&out[idx4] = r;
}

// ===================== launch ==================================================
extern "C" void kernel_launch(void* const* d_in, const int* in_sizes, int n_in,
                              void* d_out, int out_size) {
    const float* x      = (const float*)d_in[0];
    const float* w_q    = (const float*)d_in[1];
    const float* w_k    = (const float*)d_in[2];
    const float* w_sr   = (const float*)d_in[3];
    const float* sr_g   = (const float*)d_in[4];
    const float* sr_b   = (const float*)d_in[5];
    const float* sr_m   = (const float*)d_in[6];
    const float* sr_v   = (const float*)d_in[7];
    const float* w_proj = (const float*)d_in[8];
    const float* pj_g   = (const float*)d_in[9];
    const float* pj_b   = (const float*)d_in[10];
    const float* pj_m   = (const float*)d_in[11];
    const float* pj_v   = (const float*)d_in[12];
    float* out = (float*)d_out;

    u16 *qbf, *kbf, *Xt, *Xp, *wqs, *wsrs;
    float *part, *xr, *attn, *S, *vp, *v, *alpha, *bias;
    cudaGetSymbolAddress((void**)&qbf,   g_qbf);
    cudaGetSymbolAddress((void**)&kbf,   g_kbf);
    cudaGetSymbolAddress((void**)&Xt,    g_Xt);
    cudaGetSymbolAddress((void**)&Xp,    g_Xp);
    cudaGetSymbolAddress((void**)&wqs,   g_wqs);
    cudaGetSymbolAddress((void**)&wsrs,  g_wsrs);
    cudaGetSymbolAddress((void**)&part,  g_part);
    cudaGetSymbolAddress((void**)&xr,    g_xr);
    cudaGetSymbolAddress((void**)&attn,  g_attn);
    cudaGetSymbolAddress((void**)&S,     g_S);
    cudaGetSymbolAddress((void**)&vp,    g_vp);
    cudaGetSymbolAddress((void**)&v,     g_v);
    cudaGetSymbolAddress((void**)&alpha, g_alpha);
    cudaGetSymbolAddress((void**)&bias,  g_bias);

    cudaFuncSetAttribute(attn_mma, cudaFuncAttributeMaxDynamicSharedMemorySize, SM_TOT);
    cudaFuncSetAttribute(qgemm_mma, cudaFuncAttributeMaxDynamicSharedMemorySize, 32768);
    cudaFuncSetAttribute(convgemm_mma, cudaFuncAttributeMaxDynamicSharedMemorySize, 32768);
    cudaFuncSetAttribute(gather_patches, cudaFuncAttributeMaxDynamicSharedMemorySize, 32768);

    // prep
    convert_w<<<64, 256>>>(w_q, wqs);
    convert_w<<<1024, 256>>>(w_sr, wsrs);
    transpose_split_x<<<dim3(256, 4, 2), 256>>>(x, Xt, vp);
    gather_patches<<<dim3(8, 32, 2), 256, 32768>>>(x, Xp);
    // q = w_q @ x  (fp16 tensor cores)
    qgemm_mma<<<dim3(128, 2, 2), 256, 32768>>>(Xt, wqs, qbf);
    // xr = BN(conv_sr(x))  (fp16 tensor cores, split-K)
    convgemm_mma<<<dim3(8, 2, 16), 256, 32768>>>(wsrs, Xp, part);
    conv_reduce_bn<<<512, 256>>>(part, sr_g, sr_b, sr_m, sr_v, xr);
    // k = w_k @ xr (scalar, small)
    gemm_split<<<dim3(NKV / 64, CDIM / 64, BSZ), 256>>>(w_k, xr, kbf, NKV);
    // v, alpha
    vp_reduce<<<BSZ * CDIM, 256>>>(vp, v);
    alpha_kernel<<<BSZ, CDIM>>>(w_proj, v, pj_g, pj_b, pj_m, pj_v, alpha, bias);
    // attention rowmax (fp16 tensor cores)
    attn_mma<<<dim3(8, 2, 16), 256, SM_TOT>>>(qbf, kbf, attn);
    // tail
    reduce_attn<<<BSZ * NDIM / 256, 256>>>(attn, S);
    final_kernel<<<(BSZ * CDIM * NDIM / 4) / 256, 256>>>(S, alpha, bias, out);
}

// round 10
// speedup vs baseline: 1.2445x; 1.2445x over previous
#include <cuda_runtime.h>
#include <cuda_fp16.h>
#include <math.h>
#include <cstdint>

// Problem constants
#define BSZ    2
#define CDIM   256
#define NDIM   16384      // 128*128
#define HDIM   128
#define WDIM   128
#define NKV    1024       // 32*32
#define NHEADS 8
#define HD     32
#define EPSBN  1e-5f
#define KSR    4096       // CDIM*4*4

typedef unsigned long long u64;
typedef unsigned int u32;
typedef unsigned short u16;

// ===================== f32x2 helpers (scalar k GEMM) ==========================
__device__ __forceinline__ u64 pack2(float lo, float hi) {
    u64 r; asm("mov.b64 %0, {%1, %2};" : "=l"(r) : "f"(lo), "f"(hi)); return r;
}
__device__ __forceinline__ u64 fma2(u64 a, u64 b, u64 c) {
    u64 d; asm("fma.rn.f32x2 %0, %1, %2, %3;" : "=l"(d) : "l"(a), "l"(b), "l"(c)); return d;
}
__device__ __forceinline__ float2 unpack2(u64 a) {
    float lo, hi; asm("mov.b64 {%0, %1}, %2;" : "=f"(lo), "=f"(hi) : "l"(a));
    return make_float2(lo, hi);
}

// ===================== mma/ldmatrix helpers (fp16) ============================
__device__ __forceinline__ u32 smem_u32(const void* p) {
    u32 a; asm("{ .reg .u64 t; cvta.to.shared.u64 t, %1; cvt.u32.u64 %0, t; }"
               : "=r"(a) : "l"(p)); return a;
}
__device__ __forceinline__ void ldm_x4(u32 r[4], u32 addr) {
    asm volatile("ldmatrix.sync.aligned.m8n8.x4.shared.b16 {%0,%1,%2,%3}, [%4];"
                 : "=r"(r[0]), "=r"(r[1]), "=r"(r[2]), "=r"(r[3]) : "r"(addr));
}
__device__ __forceinline__ void mma_z(float& c0, float& c1, float& c2, float& c3,
                                      u32 a0, u32 a1, u32 a2, u32 a3,
                                      u32 b0, u32 b1) {
    asm volatile("mma.sync.aligned.m16n8k16.row.col.f32.f16.f16.f32 "
                 "{%0,%1,%2,%3}, {%4,%5,%6,%7}, {%8,%9}, {%10,%10,%10,%10};"
                 : "=f"(c0), "=f"(c1), "=f"(c2), "=f"(c3)
                 : "r"(a0), "r"(a1), "r"(a2), "r"(a3), "r"(b0), "r"(b1), "f"(0.0f));
}
__device__ __forceinline__ void mma_a(float& c0, float& c1, float& c2, float& c3,
                                      u32 a0, u32 a1, u32 a2, u32 a3,
                                      u32 b0, u32 b1) {
    asm volatile("mma.sync.aligned.m16n8k16.row.col.f32.f16.f16.f32 "
                 "{%0,%1,%2,%3}, {%4,%5,%6,%7}, {%8,%9}, {%0,%1,%2,%3};"
                 : "+f"(c0), "+f"(c1), "+f"(c2), "+f"(c3)
                 : "r"(a0), "r"(a1), "r"(a2), "r"(a3), "r"(b0), "r"(b1));
}
__device__ __forceinline__ u32 sw128(u32 b) { return b ^ ((b >> 3) & 0x70); }

// ===================== fp16 pack helpers ======================================
__device__ __forceinline__ u32 cvt2h(float a, float b) {
    __half2 h = __floats2half2_rn(a, b);
    return *reinterpret_cast<u32*>(&h);
}
__device__ __forceinline__ u64 cvt4h(float4 v) {
    u32 lo = cvt2h(v.x, v.y), hi = cvt2h(v.z, v.w);
    return (u64)lo | ((u64)hi << 32);
}

// ===================== scratch ================================================
__device__ __align__(16) u16  g_qbf [BSZ * NHEADS * NDIM * 32];  // fp16, 64B rows
__device__ __align__(16) u16  g_kbf [BSZ * NHEADS * NKV  * 32];  // fp16, 64B rows
__device__ __align__(16) u16  g_Xt  [BSZ * NDIM * 256];          // fp16 single
__device__ __align__(16) u16  g_Xp  [BSZ * NKV * 4096];          // fp16 single
__device__ __align__(16) u16  g_wqs [CDIM * 256];                // fp16 single
__device__ __align__(16) u16  g_wsrs[CDIM * 4096];               // fp16 single
__device__ float g_part[16 * CDIM * NKV];
__device__ float g_xr  [BSZ * CDIM * NKV];
__device__ float g_attn[2 * BSZ * NHEADS * NDIM];                // [half][bh][n]
__device__ float g_S   [BSZ * NDIM];
__device__ float g_vp  [BSZ * CDIM * 256];
__device__ float g_v   [BSZ * CDIM];
__device__ float g_alpha[BSZ * CDIM];
__device__ float g_bias [CDIM];

// ===================== prep: W fp32 -> fp16 rows ==============================
__global__ __launch_bounds__(256) void convert_w(
    const float* __restrict__ W, u16* __restrict__ out) {
    const int idx = blockIdx.x * 256 + threadIdx.x;
    const int fl = idx * 4;
    float4 v = *(const float4*)&W[fl];
    *(u64*)(out + fl) = cvt4h(v);
}

// ===================== prep: x -> Xt (tile transpose -> fp16) + v partials ====
__global__ __launch_bounds__(256) void transpose_split_x(
    const float* __restrict__ x, u16* __restrict__ Xt, float* __restrict__ vp) {
    __shared__ float s[64][65];
    const int n0 = blockIdx.x * 64;
    const int c0 = blockIdx.y * 64;
    const int b  = blockIdx.z;
    const int tid = threadIdx.x;
    #pragma unroll
    for (int i = 0; i < 4; ++i) {
        const int idx = i * 256 + tid;
        const int c_l = idx >> 4, nq = idx & 15;
        float4 v = *(const float4*)&x[((size_t)(b * CDIM + c0 + c_l)) * NDIM + n0 + nq * 4];
        s[c_l][nq * 4 + 0] = v.x; s[c_l][nq * 4 + 1] = v.y;
        s[c_l][nq * 4 + 2] = v.z; s[c_l][nq * 4 + 3] = v.w;
    }
    __syncthreads();
    const int n_l = tid >> 2, cq = tid & 3;
    u16* orow = Xt + ((size_t)(b * NDIM + n0 + n_l)) * 256 + c0;
    #pragma unroll
    for (int i = 0; i < 4; ++i) {
        const int c_loc = (cq + i * 4) * 4;
        float4 v = make_float4(s[c_loc][n_l], s[c_loc + 1][n_l],
                               s[c_loc + 2][n_l], s[c_loc + 3][n_l]);
        *(u64*)(orow + c_loc) = cvt4h(v);
    }
    if (tid < 64) {
        float acc = 0.f;
        #pragma unroll 16
        for (int n = 0; n < 64; ++n) acc += s[tid][n];
        vp[((size_t)(b * CDIM + c0 + tid)) * 256 + blockIdx.x] = acc;
    }
}

// ---------------- v = mean (reduce partials) ----------------------------------
__global__ __launch_bounds__(256) void vp_reduce(const float* __restrict__ vp,
                                                 float* __restrict__ v) {
    const int bc = blockIdx.x;
    __shared__ float red[256];
    red[threadIdx.x] = vp[(size_t)bc * 256 + threadIdx.x];
    __syncthreads();
    for (int st = 128; st > 0; st >>= 1) {
        if (threadIdx.x < st) red[threadIdx.x] += red[threadIdx.x + st];
        __syncthreads();
    }
    if (threadIdx.x == 0) v[bc] = red[0] * (1.0f / NDIM);
}

// ===================== prep: x -> Xp (patch gather -> fp16) ===================
__global__ __launch_bounds__(256) void gather_patches(
    const float* __restrict__ x, u16* __restrict__ Xp) {
    extern __shared__ char gsm[];   // 32KB
    const int cch = blockIdx.x;
    const int hh  = blockIdx.y;
    const int b   = blockIdx.z;
    const int tid = threadIdx.x;
    #pragma unroll
    for (int i = 0; i < 16; ++i) {
        const int idx = i * 256 + tid;
        const int c_l = idx >> 7;
        const int rem = idx & 127;
        const int p = rem >> 5, w4 = rem & 31;
        float4 v = *(const float4*)&x[((size_t)(b * CDIM + cch * 32 + c_l)) * NDIM
                                      + (hh * 4 + p) * WDIM + w4 * 4];
        const u32 off = (u32)(c_l * 32 + p * 8);
        const u32 phys = (off ^ ((u32)(w4 & 15) << 3)) + (u32)w4 * 1024;
        *(u64*)(gsm + phys) = cvt4h(v);
    }
    __syncthreads();
    #pragma unroll
    for (int i = 0; i < 16; ++i) {
        const int idx = i * 256 + tid;
        const int ww = idx >> 7, j = idx & 127;
        const u32 phys = (((u32)j * 8) ^ ((u32)(ww & 15) << 3)) + (u32)ww * 1024;
        u16* dst = Xp + ((size_t)(b * NKV + hh * 32 + ww)) * 4096 + cch * 512 + j * 4;
        *(u64*)dst = *(const u64*)(gsm + phys);
    }
}

// ===================== q GEMM on mma.sync (X single, W single) ================
__global__ __launch_bounds__(256, 1) void qgemm_mma(
    const u16* __restrict__ Xt, const u16* __restrict__ Wq,
    u16* __restrict__ qbf) {
    extern __shared__ char sm[];
    const u32 sb = smem_u32(sm);
    const int tid = threadIdx.x;
    const int l = tid & 31, wid = tid >> 5;
    const int wm = wid & 3, wo = wid >> 2;
    const int blkn = blockIdx.x, blko = blockIdx.y, bb = blockIdx.z;

    const u16* XtB = Xt + (size_t)(bb * NDIM + blkn * 128) * 256;
    const u16* WqB = Wq + (size_t)(blko * 128) * 256;

    float acc[2][8][4];
    #pragma unroll
    for (int a = 0; a < 2; ++a)
        #pragma unroll
        for (int c = 0; c < 8; ++c)
            #pragma unroll
            for (int d = 0; d < 4; ++d) acc[a][c][d] = 0.f;

    u32 rowA[2], rowB[4];
    #pragma unroll
    for (int mt = 0; mt < 2; ++mt)
        rowA[mt] = (u32)(wm * 32 + mt * 16 + (l & 7) + (l & 8)) * 128;
    #pragma unroll
    for (int g = 0; g < 4; ++g)
        rowB[g] = (u32)(wo * 64 + g * 16 + (l & 7) + ((l & 16) >> 1)) * 128;

    for (int kc = 0; kc < 4; ++kc) {
        for (int i = tid; i < 1024; i += 256) {
            const int row = i >> 3, ch = i & 7;
            const u32 dst = sw128((u32)(row * 128 + ch * 16));
            const size_t off = (size_t)row * 256 + kc * 64 + ch * 8;
            *(uint4*)(sm + dst)         = *(const uint4*)(XtB + off);
            *(uint4*)(sm + 16384 + dst) = *(const uint4*)(WqB + off);
        }
        __syncthreads();
        #pragma unroll
        for (int s = 0; s < 4; ++s) {
            const u32 cA = ((u32)((2 * s + ((l >> 4) & 1)) ^ (l & 7))) << 4;
            const u32 cB = ((u32)((2 * s + ((l >> 3) & 1)) ^ (l & 7))) << 4;
            u32 a[2][4], bf[4][4];
            #pragma unroll
            for (int mt = 0; mt < 2; ++mt)
                ldm_x4(a[mt], sb + rowA[mt] + cA);
            #pragma unroll
            for (int g = 0; g < 4; ++g)
                ldm_x4(bf[g], sb + 16384 + rowB[g] + cB);
            #pragma unroll
            for (int mt = 0; mt < 2; ++mt)
                #pragma unroll
                for (int g = 0; g < 4; ++g)
                    #pragma unroll
                    for (int hf = 0; hf < 2; ++hf) {
                        float* A4 = acc[mt][g * 2 + hf];
                        mma_a(A4[0], A4[1], A4[2], A4[3],
                              a[mt][0], a[mt][1], a[mt][2], a[mt][3],
                              bf[g][2 * hf], bf[g][2 * hf + 1]);
                    }
        }
        __syncthreads();
    }

    // epilogue: single fp16 q rows (32 fp16 = 64B)
    #pragma unroll
    for (int mt = 0; mt < 2; ++mt) {
        const int n0g = blkn * 128 + wm * 32 + mt * 16 + (l >> 2);
        #pragma unroll
        for (int nt = 0; nt < 8; ++nt) {
            const int o = blko * 128 + wo * 64 + nt * 8 + 2 * (l & 3);
            const int bh_ = bb * NHEADS + (o >> 5);
            const int d = o & 31;
            u16* base = qbf + ((size_t)bh_ * NDIM + n0g) * 32 + d;
            *(u32*)base = cvt2h(acc[mt][nt][0], acc[mt][nt][1]);
            *(u32*)(base + 8 * 32) = cvt2h(acc[mt][nt][2], acc[mt][nt][3]);
        }
    }
}

// ===================== conv GEMM on mma.sync (single fp16, split-K=8) =========
__global__ __launch_bounds__(256, 1) void convgemm_mma(
    const u16* __restrict__ Wsr, const u16* __restrict__ Xp,
    float* __restrict__ part) {
    extern __shared__ char sm[];
    const u32 sb = smem_u32(sm);
    const int tid = threadIdx.x;
    const int l = tid & 31, wid = tid >> 5;
    const int wm = wid & 3, wo = wid >> 2;
    const int blkm = blockIdx.x, blko = blockIdx.y;
    const int zz = blockIdx.z;
    const int bb = zz & 1, ks = zz >> 1;

    const u16* AB = Wsr + (size_t)(blko * 128) * 4096;
    const u16* BB = Xp + (size_t)(bb * NKV + blkm * 128) * 4096;

    float acc[2][8][4];
    #pragma unroll
    for (int a = 0; a < 2; ++a)
        #pragma unroll
        for (int c = 0; c < 8; ++c)
            #pragma unroll
            for (int d = 0; d < 4; ++d) acc[a][c][d] = 0.f;

    u32 rowA[2], rowB[4];
    #pragma unroll
    for (int mt = 0; mt < 2; ++mt)
        rowA[mt] = (u32)(wm * 32 + mt * 16 + (l & 7) + (l & 8)) * 128;
    #pragma unroll
    for (int g = 0; g < 4; ++g)
        rowB[g] = (u32)(wo * 64 + g * 16 + (l & 7) + ((l & 16) >> 1)) * 128;

    for (int kcl = 0; kcl < 8; ++kcl) {
        const int kcg = ks * 8 + kcl;
        for (int i = tid; i < 1024; i += 256) {
            const int row = i >> 3, ch = i & 7;
            const u32 dst = sw128((u32)(row * 128 + ch * 16));
            const size_t off = (size_t)row * 4096 + kcg * 64 + ch * 8;
            *(uint4*)(sm + dst)         = *(const uint4*)(AB + off);
            *(uint4*)(sm + 16384 + dst) = *(const uint4*)(BB + off);
        }
        __syncthreads();
        #pragma unroll
        for (int s = 0; s < 4; ++s) {
            const u32 cA = ((u32)((2 * s + ((l >> 4) & 1)) ^ (l & 7))) << 4;
            const u32 cB = ((u32)((2 * s + ((l >> 3) & 1)) ^ (l & 7))) << 4;
            u32 a[2][4], bf[4][4];
            #pragma unroll
            for (int mt = 0; mt < 2; ++mt)
                ldm_x4(a[mt], sb + rowA[mt] + cA);
            #pragma unroll
            for (int g = 0; g < 4; ++g)
                ldm_x4(bf[g], sb + 16384 + rowB[g] + cB);
            #pragma unroll
            for (int mt = 0; mt < 2; ++mt)
                #pragma unroll
                for (int g = 0; g < 4; ++g)
                    #pragma unroll
                    for (int hf = 0; hf < 2; ++hf) {
                        float* A4 = acc[mt][g * 2 + hf];
                        mma_a(A4[0], A4[1], A4[2], A4[3],
                              a[mt][0], a[mt][1], a[mt][2], a[mt][3],
                              bf[g][2 * hf], bf[g][2 * hf + 1]);
                    }
        }
        __syncthreads();
    }

    #pragma unroll
    for (int mt = 0; mt < 2; ++mt) {
        const int o = blko * 128 + wm * 32 + mt * 16 + (l >> 2);
        #pragma unroll
        for (int nt = 0; nt < 8; ++nt) {
            const int m = blkm * 128 + wo * 64 + nt * 8 + 2 * (l & 3);
            float* dst = part + ((size_t)zz * CDIM + o) * NKV + m;
            *(float2*)dst = make_float2(acc[mt][nt][0], acc[mt][nt][1]);
            *(float2*)(dst + 8 * NKV) = make_float2(acc[mt][nt][2], acc[mt][nt][3]);
        }
    }
}

// ===================== conv reduce + BN =======================================
__global__ __launch_bounds__(256) void conv_reduce_bn(
    const float* __restrict__ part,
    const float* __restrict__ gam, const float* __restrict__ bet,
    const float* __restrict__ mu,  const float* __restrict__ var,
    float* __restrict__ xr) {
    const int idx = blockIdx.x * 256 + threadIdx.x;
    const int fl = idx * 4;
    const int b = fl >> 18;
    const int o = (fl >> 10) & 255;
    const int m = fl & 1023;
    float4 s = make_float4(0.f, 0.f, 0.f, 0.f);
    #pragma unroll
    for (int ks = 0; ks < 8; ++ks) {
        const float4 p = *(const float4*)&part[((size_t)(ks * 2 + b) * CDIM + o) * NKV + m];
        s.x += p.x; s.y += p.y; s.z += p.z; s.w += p.w;
    }
    const float inv = gam[o] * rsqrtf(var[o] + EPSBN);
    const float mb = mu[o], be = bet[o];
    float4 r = make_float4((s.x - mb) * inv + be, (s.y - mb) * inv + be,
                           (s.z - mb) * inv + be, (s.w - mb) * inv + be);
    *(float4*)&xr[((size_t)(b * CDIM + o)) * NKV + m] = r;
}

// ===================== k GEMM (scalar f32x2, fp16 epilogue) ===================
__global__ __launch_bounds__(256) void gemm_split(
    const float* __restrict__ W, const float* __restrict__ X,
    u16* __restrict__ Out, int Ncol) {
    __shared__ float As[16][64];
    __shared__ float Bs[16][64];
    const int b  = blockIdx.z;
    const float* Xb = X + (size_t)b * CDIM * Ncol;
    const int bm = blockIdx.y * 64;
    const int bn = blockIdx.x * 64;
    const int tid = threadIdx.x;
    const int tm = tid >> 4, tn = tid & 15;

    u64 acc[4][2] = {};
    for (int k0 = 0; k0 < CDIM; k0 += 16) {
        const int ar = tid >> 2, ac = (tid & 3) * 4;
        float4 a4 = *(const float4*)&W[(size_t)(bm + ar) * CDIM + k0 + ac];
        As[ac + 0][ar] = a4.x; As[ac + 1][ar] = a4.y;
        As[ac + 2][ar] = a4.z; As[ac + 3][ar] = a4.w;
        const int br = tid >> 4, bc = (tid & 15) * 4;
        *(float4*)&Bs[br][bc] = *(const float4*)&Xb[(size_t)(k0 + br) * Ncol + bn + bc];
        __syncthreads();
        #pragma unroll
        for (int kk = 0; kk < 16; ++kk) {
            float4 av = *(const float4*)&As[kk][tm * 4];
            ulonglong2 bv = *(const ulonglong2*)&Bs[kk][tn * 4];
            u64 a0 = pack2(av.x, av.x), a1 = pack2(av.y, av.y);
            u64 a2 = pack2(av.z, av.z), a3 = pack2(av.w, av.w);
            acc[0][0] = fma2(a0, bv.x, acc[0][0]); acc[0][1] = fma2(a0, bv.y, acc[0][1]);
            acc[1][0] = fma2(a1, bv.x, acc[1][0]); acc[1][1] = fma2(a1, bv.y, acc[1][1]);
            acc[2][0] = fma2(a2, bv.x, acc[2][0]); acc[2][1] = fma2(a2, bv.y, acc[2][1]);
            acc[3][0] = fma2(a3, bv.x, acc[3][0]); acc[3][1] = fma2(a3, bv.y, acc[3][1]);
        }
        __syncthreads();
    }
    const int o0 = bm + tm * 4;        // 4 consecutive o (same head), multiple of 4
    const int d0 = o0 & 31;
    const int bh = b * NHEADS + (o0 >> 5);
    #pragma unroll
    for (int j = 0; j < 4; ++j) {
        const int col = bn + tn * 4 + j;
        float vs[4];
        #pragma unroll
        for (int i = 0; i < 4; ++i) {
            float2 f = unpack2(acc[i][j >> 1]);
            vs[i] = (j & 1) ? f.y : f.x;
        }
        u16* base = Out + ((size_t)bh * Ncol + col) * 32 + d0;
        *(u64*)base = cvt4h(make_float4(vs[0], vs[1], vs[2], vs[3]));
    }
}

// ---------------- alpha/bias --------------------------------------------------
__global__ __launch_bounds__(256) void alpha_kernel(
    const float* __restrict__ wproj, const float* __restrict__ v,
    const float* __restrict__ gam, const float* __restrict__ bet,
    const float* __restrict__ mu,  const float* __restrict__ var,
    float* __restrict__ alpha, float* __restrict__ bias) {
    const int b = blockIdx.x;
    const int o = threadIdx.x;
    __shared__ float vs[CDIM];
    vs[o] = v[b * CDIM + o];
    __syncthreads();
    float p = 0.f;
    const float* wr = wproj + (size_t)o * CDIM;
    #pragma unroll 8
    for (int c = 0; c < CDIM; ++c) p = fmaf(wr[c], vs[c], p);
    const float inv = gam[o] * rsqrtf(var[o] + EPSBN);
    alpha[b * CDIM + o] = p * inv;
    if (b == 0) bias[o] = bet[o] - mu[o] * inv;
}

// ===================== fp16 mma.sync attention (kv-split) =====================
// grid (seg 8, half 2, bh 16); 256 threads; smem = k 32KB + q 8KB = 40KB.
#define SM_QOFF 32768
#define SM_TOT  40960
#define NTILES  16

__global__ __launch_bounds__(256, 2)
void attn_mma(const u16* __restrict__ qbf, const u16* __restrict__ kbf,
              float* __restrict__ attn) {
    extern __shared__ char smem[];
    const u32 sb  = smem_u32(smem);
    const int tid = threadIdx.x;
    const int wid = tid >> 5, l = tid & 31;
    const int seg  = blockIdx.x;
    const int half = blockIdx.y;
    const int bh   = blockIdx.z;

    // stage this half's k (512 rows x 64B)
    {
        const uint4* ksrc = (const uint4*)(kbf + (size_t)(bh * NKV + half * 512) * 32);
        for (int idx = tid; idx < 512 * 4; idx += 256) {
            const int row = idx >> 2, c = idx & 3;
            const u32 off = (u32)((row >> 1) * 128 + (row & 1) * 64 + c * 16);
            *(uint4*)(smem + sw128(off)) = ksrc[idx];
        }
    }
    __syncthreads();

    const int brow = (l & 7) + ((l & 16) >> 1);
    u32 baddr[2];
    #pragma unroll
    for (int s = 0; s < 2; ++s) {
        const u32 off = (u32)((brow >> 1) * 128 + (brow & 1) * 64
                              + (2 * s + ((l >> 3) & 1)) * 16);
        baddr[s] = sb + sw128(off);
    }
    const int Rr = wid * 16 + (l & 15);
    u32 aaddr[2];
    #pragma unroll
    for (int s = 0; s < 2; ++s) {
        const u32 off = (u32)((Rr >> 1) * 128 + (Rr & 1) * 64 + (2 * s + (l >> 4)) * 16);
        aaddr[s] = sb + SM_QOFF + sw128(off);
    }

    const float scale = 0.17677669529663687f;
    float* ob = attn + ((size_t)(half * 16 + bh)) * NDIM;

    for (int t = 0; t < NTILES; ++t) {
        const int n_base = (seg * NTILES + t) * 128;
        {
            const uint4* qsrc = (const uint4*)(qbf + ((size_t)bh * NDIM + n_base) * 32);
            const int row = tid >> 1;
            const int c0 = (tid & 1) * 2;
            #pragma unroll
            for (int j = 0; j < 2; ++j) {
                const int c = c0 + j;
                const u32 off = (u32)((row >> 1) * 128 + (row & 1) * 64 + c * 16);
                *(uint4*)(smem + SM_QOFF + sw128(off)) = qsrc[(size_t)row * 4 + c];
            }
        }
        __syncwarp();

        u32 a[2][4];
        ldm_x4(a[0], aaddr[0]);
        ldm_x4(a[1], aaddr[1]);
        __syncwarp();

        float rmax[2] = {-INFINITY, -INFINITY};
        for (int kv = 0; kv < 32; ++kv) {
            const u32 off = (u32)kv * 1024;
            u32 b0[4], b1[4];
            ldm_x4(b0, baddr[0] + off);
            ldm_x4(b1, baddr[1] + off);
            #pragma unroll
            for (int g = 0; g < 2; ++g) {
                float A0, A1, A2, A3, B0, B1, B2, B3;
                mma_z(A0, A1, A2, A3, a[0][0], a[0][1], a[0][2], a[0][3],
                      b0[2 * g], b0[2 * g + 1]);
                mma_z(B0, B1, B2, B3, a[1][0], a[1][1], a[1][2], a[1][3],
                      b1[2 * g], b1[2 * g + 1]);
                rmax[0] = fmaxf(rmax[0], fmaxf(A0 + B0, A1 + B1));
                rmax[1] = fmaxf(rmax[1], fmaxf(A2 + B2, A3 + B3));
            }
        }
        #pragma unroll
        for (int rr = 0; rr < 2; ++rr) {
            float v = rmax[rr];
            v = fmaxf(v, __shfl_xor_sync(0xffffffffu, v, 1));
            v = fmaxf(v, __shfl_xor_sync(0xffffffffu, v, 2));
            rmax[rr] = v;
        }
        if ((l & 3) == 0) {
            const int rbase = n_base + wid * 16;
            ob[rbase + (l >> 2) + 0] = rmax[0] * scale;
            ob[rbase + (l >> 2) + 8] = rmax[1] * scale;
        }
        __syncwarp();
    }
}

// ---------------- S[b][n] = sum_h max(half0, half1) ---------------------------
__global__ __launch_bounds__(256) void reduce_attn(const float* __restrict__ attn,
                                                   float* __restrict__ S) {
    const int idx = blockIdx.x * 256 + threadIdx.x;
    const int b = idx >> 14, n = idx & (NDIM - 1);
    float s = 0.f;
    #pragma unroll
    for (int h = 0; h < NHEADS; ++h) {
        const size_t base = ((size_t)(b * NHEADS + h)) * NDIM + n;
        s += fmaxf(attn[base], attn[base + (size_t)16 * NDIM]);
    }
    S[idx] = s;
}

// ---------------- out = alpha*S + bias -----------------------------------------
__global__ __launch_bounds__(256) void final_kernel(
    const float* __restrict__ S, const float* __restrict__ alpha,
    const float* __restrict__ bias, float* __restrict__ out) {
    const size_t t = (size_t)blockIdx.x * 256 + threadIdx.x;
    const size_t idx4 = t * 4;
    const int bo = (int)(idx4 >> 14);
    const int n  = (int)(idx4 & (NDIM - 1));
    const int b  = bo >> 8, o = bo & 255;
    const float a  = alpha[bo];
    const float bi = bias[o];
    float4 s = *(const float4*)&S[(size_t)b * NDIM + n];
    float4 r;
    r.x = fmaf(a, s.x, bi); r.y = fmaf(a, s.y, bi);
    r.z = fmaf(a, s.z, bi); r.w = fmaf(a, s.w, bi);
    *(float4*)&out[idx4] = r;
}

// ===================== launch ==================================================
extern "C" void kernel_launch(void* const* d_in, const int* in_sizes, int n_in,
                              void* d_out, int out_size) {
    const float* x      = (const float*)d_in[0];
    const float* w_q    = (const float*)d_in[1];
    const float* w_k    = (const float*)d_in[2];
    const float* w_sr   = (const float*)d_in[3];
    const float* sr_g   = (const float*)d_in[4];
    const float* sr_b   = (const float*)d_in[5];
    const float* sr_m   = (const float*)d_in[6];
    const float* sr_v   = (const float*)d_in[7];
    const float* w_proj = (const float*)d_in[8];
    const float* pj_g   = (const float*)d_in[9];
    const float* pj_b   = (const float*)d_in[10];
    const float* pj_m   = (const float*)d_in[11];
    const float* pj_v   = (const float*)d_in[12];
    float* out = (float*)d_out;

    u16 *qbf, *kbf, *Xt, *Xp, *wqs, *wsrs;
    float *part, *xr, *attn, *S, *vp, *v, *alpha, *bias;
    cudaGetSymbolAddress((void**)&qbf,   g_qbf);
    cudaGetSymbolAddress((void**)&kbf,   g_kbf);
    cudaGetSymbolAddress((void**)&Xt,    g_Xt);
    cudaGetSymbolAddress((void**)&Xp,    g_Xp);
    cudaGetSymbolAddress((void**)&wqs,   g_wqs);
    cudaGetSymbolAddress((void**)&wsrs,  g_wsrs);
    cudaGetSymbolAddress((void**)&part,  g_part);
    cudaGetSymbolAddress((void**)&xr,    g_xr);
    cudaGetSymbolAddress((void**)&attn,  g_attn);
    cudaGetSymbolAddress((void**)&S,     g_S);
    cudaGetSymbolAddress((void**)&vp,    g_vp);
    cudaGetSymbolAddress((void**)&v,     g_v);
    cudaGetSymbolAddress((void**)&alpha, g_alpha);
    cudaGetSymbolAddress((void**)&bias,  g_bias);

    cudaFuncSetAttribute(attn_mma, cudaFuncAttributeMaxDynamicSharedMemorySize, SM_TOT);
    cudaFuncSetAttribute(qgemm_mma, cudaFuncAttributeMaxDynamicSharedMemorySize, 32768);
    cudaFuncSetAttribute(convgemm_mma, cudaFuncAttributeMaxDynamicSharedMemorySize, 32768);
    cudaFuncSetAttribute(gather_patches, cudaFuncAttributeMaxDynamicSharedMemorySize, 32768);

    // prep
    convert_w<<<64, 256>>>(w_q, wqs);
    convert_w<<<1024, 256>>>(w_sr, wsrs);
    transpose_split_x<<<dim3(256, 4, 2), 256>>>(x, Xt, vp);
    gather_patches<<<dim3(8, 32, 2), 256, 32768>>>(x, Xp);
    // q = w_q @ x  (fp16 tensor cores)
    qgemm_mma<<<dim3(128, 2, 2), 256, 32768>>>(Xt, wqs, qbf);
    // xr = BN(conv_sr(x))  (fp16 tensor cores, split-K)
    convgemm_mma<<<dim3(8, 2, 16), 256, 32768>>>(wsrs, Xp, part);
    conv_reduce_bn<<<512, 256>>>(part, sr_g, sr_b, sr_m, sr_v, xr);
    // k = w_k @ xr (scalar, small)
    gemm_split<<<dim3(NKV / 64, CDIM / 64, BSZ), 256>>>(w_k, xr, kbf, NKV);
    // v, alpha
    vp_reduce<<<BSZ * CDIM, 256>>>(vp, v);
    alpha_kernel<<<BSZ, CDIM>>>(w_proj, v, pj_g, pj_b, pj_m, pj_v, alpha, bias);
    // attention rowmax (fp16 tensor cores)
    attn_mma<<<dim3(8, 2, 16), 256, SM_TOT>>>(qbf, kbf, attn);
    // tail
    reduce_attn<<<BSZ * NDIM / 256, 256>>>(attn, S);
    final_kernel<<<(BSZ * CDIM * NDIM / 4) / 256, 256>>>(S, alpha, bias, out);
}

// round 11
// speedup vs baseline: 1.2647x; 1.0163x over previous
#include <cuda_runtime.h>
#include <cuda_fp16.h>
#include <math.h>
#include <cstdint>

// Problem constants
#define BSZ    2
#define CDIM   256
#define NDIM   16384      // 128*128
#define HDIM   128
#define WDIM   128
#define NKV    1024       // 32*32
#define NHEADS 8
#define HD     32
#define EPSBN  1e-5f
#define KSR    4096       // CDIM*4*4

typedef unsigned long long u64;
typedef unsigned int u32;
typedef unsigned short u16;

// ===================== f32x2 helpers (scalar k GEMM) ==========================
__device__ __forceinline__ u64 pack2(float lo, float hi) {
    u64 r; asm("mov.b64 %0, {%1, %2};" : "=l"(r) : "f"(lo), "f"(hi)); return r;
}
__device__ __forceinline__ u64 fma2(u64 a, u64 b, u64 c) {
    u64 d; asm("fma.rn.f32x2 %0, %1, %2, %3;" : "=l"(d) : "l"(a), "l"(b), "l"(c)); return d;
}
__device__ __forceinline__ float2 unpack2(u64 a) {
    float lo, hi; asm("mov.b64 {%0, %1}, %2;" : "=f"(lo), "=f"(hi) : "l"(a));
    return make_float2(lo, hi);
}

// ===================== mma/ldmatrix helpers (fp16) ============================
__device__ __forceinline__ u32 smem_u32(const void* p) {
    u32 a; asm("{ .reg .u64 t; cvta.to.shared.u64 t, %1; cvt.u32.u64 %0, t; }"
               : "=r"(a) : "l"(p)); return a;
}
__device__ __forceinline__ void ldm_x4(u32 r[4], u32 addr) {
    asm volatile("ldmatrix.sync.aligned.m8n8.x4.shared.b16 {%0,%1,%2,%3}, [%4];"
                 : "=r"(r[0]), "=r"(r[1]), "=r"(r[2]), "=r"(r[3]) : "r"(addr));
}
__device__ __forceinline__ void mma_a(float& c0, float& c1, float& c2, float& c3,
                                      u32 a0, u32 a1, u32 a2, u32 a3,
                                      u32 b0, u32 b1) {
    asm volatile("mma.sync.aligned.m16n8k16.row.col.f32.f16.f16.f32 "
                 "{%0,%1,%2,%3}, {%4,%5,%6,%7}, {%8,%9}, {%0,%1,%2,%3};"
                 : "+f"(c0), "+f"(c1), "+f"(c2), "+f"(c3)
                 : "r"(a0), "r"(a1), "r"(a2), "r"(a3), "r"(b0), "r"(b1));
}
// fp16-accumulator MMA, zero C: output packed half2 x2
__device__ __forceinline__ void mma_h(u32& d0, u32& d1,
                                      u32 a0, u32 a1, u32 a2, u32 a3,
                                      u32 b0, u32 b1) {
    asm volatile("mma.sync.aligned.m16n8k16.row.col.f16.f16.f16.f16 "
                 "{%0,%1}, {%2,%3,%4,%5}, {%6,%7}, {%8,%8};"
                 : "=r"(d0), "=r"(d1)
                 : "r"(a0), "r"(a1), "r"(a2), "r"(a3), "r"(b0), "r"(b1), "r"(0u));
}
__device__ __forceinline__ u32 hadd2u(u32 a, u32 b) {
    u32 d; asm("add.f16x2 %0, %1, %2;" : "=r"(d) : "r"(a), "r"(b)); return d;
}
__device__ __forceinline__ u32 hmax2u(u32 a, u32 b) {
    u32 d; asm("max.f16x2 %0, %1, %2;" : "=r"(d) : "r"(a), "r"(b)); return d;
}
__device__ __forceinline__ u32 sw128(u32 b) { return b ^ ((b >> 3) & 0x70); }

// ===================== fp16 pack helpers ======================================
__device__ __forceinline__ u32 cvt2h(float a, float b) {
    __half2 h = __floats2half2_rn(a, b);
    return *reinterpret_cast<u32*>(&h);
}
__device__ __forceinline__ u64 cvt4h(float4 v) {
    u32 lo = cvt2h(v.x, v.y), hi = cvt2h(v.z, v.w);
    return (u64)lo | ((u64)hi << 32);
}

// ===================== scratch ================================================
__device__ __align__(16) u16  g_qbf [BSZ * NHEADS * NDIM * 32];  // fp16, 64B rows
__device__ __align__(16) u16  g_kbf [BSZ * NHEADS * NKV  * 32];  // fp16, 64B rows
__device__ __align__(16) u16  g_Xt  [BSZ * NDIM * 256];          // fp16 single
__device__ __align__(16) u16  g_Xp  [BSZ * NKV * 4096];          // fp16 single
__device__ __align__(16) u16  g_wqs [CDIM * 256];                // fp16 single
__device__ __align__(16) u16  g_wsrs[CDIM * 4096];               // fp16 single
__device__ float g_part[16 * CDIM * NKV];
__device__ float g_xr  [BSZ * CDIM * NKV];
__device__ float g_attn[2 * BSZ * NHEADS * NDIM];                // [half][bh][n]
__device__ float g_S   [BSZ * NDIM];
__device__ float g_vp  [BSZ * CDIM * 256];
__device__ float g_v   [BSZ * CDIM];
__device__ float g_alpha[BSZ * CDIM];
__device__ float g_bias [CDIM];

// ===================== prep: W fp32 -> fp16 rows ==============================
__global__ __launch_bounds__(256) void convert_w(
    const float* __restrict__ W, u16* __restrict__ out) {
    const int idx = blockIdx.x * 256 + threadIdx.x;
    const int fl = idx * 4;
    float4 v = *(const float4*)&W[fl];
    *(u64*)(out + fl) = cvt4h(v);
}

// ===================== prep: x -> Xt (tile transpose -> fp16) + v partials ====
__global__ __launch_bounds__(256) void transpose_split_x(
    const float* __restrict__ x, u16* __restrict__ Xt, float* __restrict__ vp) {
    __shared__ float s[64][65];
    const int n0 = blockIdx.x * 64;
    const int c0 = blockIdx.y * 64;
    const int b  = blockIdx.z;
    const int tid = threadIdx.x;
    #pragma unroll
    for (int i = 0; i < 4; ++i) {
        const int idx = i * 256 + tid;
        const int c_l = idx >> 4, nq = idx & 15;
        float4 v = *(const float4*)&x[((size_t)(b * CDIM + c0 + c_l)) * NDIM + n0 + nq * 4];
        s[c_l][nq * 4 + 0] = v.x; s[c_l][nq * 4 + 1] = v.y;
        s[c_l][nq * 4 + 2] = v.z; s[c_l][nq * 4 + 3] = v.w;
    }
    __syncthreads();
    const int n_l = tid >> 2, cq = tid & 3;
    u16* orow = Xt + ((size_t)(b * NDIM + n0 + n_l)) * 256 + c0;
    #pragma unroll
    for (int i = 0; i < 4; ++i) {
        const int c_loc = (cq + i * 4) * 4;
        float4 v = make_float4(s[c_loc][n_l], s[c_loc + 1][n_l],
                               s[c_loc + 2][n_l], s[c_loc + 3][n_l]);
        *(u64*)(orow + c_loc) = cvt4h(v);
    }
    if (tid < 64) {
        float acc = 0.f;
        #pragma unroll 16
        for (int n = 0; n < 64; ++n) acc += s[tid][n];
        vp[((size_t)(b * CDIM + c0 + tid)) * 256 + blockIdx.x] = acc;
    }
}

// ---------------- v = mean (reduce partials) ----------------------------------
__global__ __launch_bounds__(256) void vp_reduce(const float* __restrict__ vp,
                                                 float* __restrict__ v) {
    const int bc = blockIdx.x;
    __shared__ float red[256];
    red[threadIdx.x] = vp[(size_t)bc * 256 + threadIdx.x];
    __syncthreads();
    for (int st = 128; st > 0; st >>= 1) {
        if (threadIdx.x < st) red[threadIdx.x] += red[threadIdx.x + st];
        __syncthreads();
    }
    if (threadIdx.x == 0) v[bc] = red[0] * (1.0f / NDIM);
}

// ===================== prep: x -> Xp (patch gather -> fp16) ===================
__global__ __launch_bounds__(256) void gather_patches(
    const float* __restrict__ x, u16* __restrict__ Xp) {
    extern __shared__ char gsm[];   // 32KB
    const int cch = blockIdx.x;
    const int hh  = blockIdx.y;
    const int b   = blockIdx.z;
    const int tid = threadIdx.x;
    #pragma unroll
    for (int i = 0; i < 16; ++i) {
        const int idx = i * 256 + tid;
        const int c_l = idx >> 7;
        const int rem = idx & 127;
        const int p = rem >> 5, w4 = rem & 31;
        float4 v = *(const float4*)&x[((size_t)(b * CDIM + cch * 32 + c_l)) * NDIM
                                      + (hh * 4 + p) * WDIM + w4 * 4];
        const u32 off = (u32)(c_l * 32 + p * 8);
        const u32 phys = (off ^ ((u32)(w4 & 15) << 3)) + (u32)w4 * 1024;
        *(u64*)(gsm + phys) = cvt4h(v);
    }
    __syncthreads();
    #pragma unroll
    for (int i = 0; i < 16; ++i) {
        const int idx = i * 256 + tid;
        const int ww = idx >> 7, j = idx & 127;
        const u32 phys = (((u32)j * 8) ^ ((u32)(ww & 15) << 3)) + (u32)ww * 1024;
        u16* dst = Xp + ((size_t)(b * NKV + hh * 32 + ww)) * 4096 + cch * 512 + j * 4;
        *(u64*)dst = *(const u64*)(gsm + phys);
    }
}

// ===================== q GEMM on mma.sync (X single, W single) ================
__global__ __launch_bounds__(256, 1) void qgemm_mma(
    const u16* __restrict__ Xt, const u16* __restrict__ Wq,
    u16* __restrict__ qbf) {
    extern __shared__ char sm[];
    const u32 sb = smem_u32(sm);
    const int tid = threadIdx.x;
    const int l = tid & 31, wid = tid >> 5;
    const int wm = wid & 3, wo = wid >> 2;
    const int blkn = blockIdx.x, blko = blockIdx.y, bb = blockIdx.z;

    const u16* XtB = Xt + (size_t)(bb * NDIM + blkn * 128) * 256;
    const u16* WqB = Wq + (size_t)(blko * 128) * 256;

    float acc[2][8][4];
    #pragma unroll
    for (int a = 0; a < 2; ++a)
        #pragma unroll
        for (int c = 0; c < 8; ++c)
            #pragma unroll
            for (int d = 0; d < 4; ++d) acc[a][c][d] = 0.f;

    u32 rowA[2], rowB[4];
    #pragma unroll
    for (int mt = 0; mt < 2; ++mt)
        rowA[mt] = (u32)(wm * 32 + mt * 16 + (l & 7) + (l & 8)) * 128;
    #pragma unroll
    for (int g = 0; g < 4; ++g)
        rowB[g] = (u32)(wo * 64 + g * 16 + (l & 7) + ((l & 16) >> 1)) * 128;

    for (int kc = 0; kc < 4; ++kc) {
        for (int i = tid; i < 1024; i += 256) {
            const int row = i >> 3, ch = i & 7;
            const u32 dst = sw128((u32)(row * 128 + ch * 16));
            const size_t off = (size_t)row * 256 + kc * 64 + ch * 8;
            *(uint4*)(sm + dst)         = *(const uint4*)(XtB + off);
            *(uint4*)(sm + 16384 + dst) = *(const uint4*)(WqB + off);
        }
        __syncthreads();
        #pragma unroll
        for (int s = 0; s < 4; ++s) {
            const u32 cA = ((u32)((2 * s + ((l >> 4) & 1)) ^ (l & 7))) << 4;
            const u32 cB = ((u32)((2 * s + ((l >> 3) & 1)) ^ (l & 7))) << 4;
            u32 a[2][4], bf[4][4];
            #pragma unroll
            for (int mt = 0; mt < 2; ++mt)
                ldm_x4(a[mt], sb + rowA[mt] + cA);
            #pragma unroll
            for (int g = 0; g < 4; ++g)
                ldm_x4(bf[g], sb + 16384 + rowB[g] + cB);
            #pragma unroll
            for (int mt = 0; mt < 2; ++mt)
                #pragma unroll
                for (int g = 0; g < 4; ++g)
                    #pragma unroll
                    for (int hf = 0; hf < 2; ++hf) {
                        float* A4 = acc[mt][g * 2 + hf];
                        mma_a(A4[0], A4[1], A4[2], A4[3],
                              a[mt][0], a[mt][1], a[mt][2], a[mt][3],
                              bf[g][2 * hf], bf[g][2 * hf + 1]);
                    }
        }
        __syncthreads();
    }

    // epilogue: single fp16 q rows (32 fp16 = 64B)
    #pragma unroll
    for (int mt = 0; mt < 2; ++mt) {
        const int n0g = blkn * 128 + wm * 32 + mt * 16 + (l >> 2);
        #pragma unroll
        for (int nt = 0; nt < 8; ++nt) {
            const int o = blko * 128 + wo * 64 + nt * 8 + 2 * (l & 3);
            const int bh_ = bb * NHEADS + (o >> 5);
            const int d = o & 31;
            u16* base = qbf + ((size_t)bh_ * NDIM + n0g) * 32 + d;
            *(u32*)base = cvt2h(acc[mt][nt][0], acc[mt][nt][1]);
            *(u32*)(base + 8 * 32) = cvt2h(acc[mt][nt][2], acc[mt][nt][3]);
        }
    }
}

// ===================== conv GEMM on mma.sync (single fp16, split-K=8) =========
__global__ __launch_bounds__(256, 1) void convgemm_mma(
    const u16* __restrict__ Wsr, const u16* __restrict__ Xp,
    float* __restrict__ part) {
    extern __shared__ char sm[];
    const u32 sb = smem_u32(sm);
    const int tid = threadIdx.x;
    const int l = tid & 31, wid = tid >> 5;
    const int wm = wid & 3, wo = wid >> 2;
    const int blkm = blockIdx.x, blko = blockIdx.y;
    const int zz = blockIdx.z;
    const int bb = zz & 1, ks = zz >> 1;

    const u16* AB = Wsr + (size_t)(blko * 128) * 4096;
    const u16* BB = Xp + (size_t)(bb * NKV + blkm * 128) * 4096;

    float acc[2][8][4];
    #pragma unroll
    for (int a = 0; a < 2; ++a)
        #pragma unroll
        for (int c = 0; c < 8; ++c)
            #pragma unroll
            for (int d = 0; d < 4; ++d) acc[a][c][d] = 0.f;

    u32 rowA[2], rowB[4];
    #pragma unroll
    for (int mt = 0; mt < 2; ++mt)
        rowA[mt] = (u32)(wm * 32 + mt * 16 + (l & 7) + (l & 8)) * 128;
    #pragma unroll
    for (int g = 0; g < 4; ++g)
        rowB[g] = (u32)(wo * 64 + g * 16 + (l & 7) + ((l & 16) >> 1)) * 128;

    for (int kcl = 0; kcl < 8; ++kcl) {
        const int kcg = ks * 8 + kcl;
        for (int i = tid; i < 1024; i += 256) {
            const int row = i >> 3, ch = i & 7;
            const u32 dst = sw128((u32)(row * 128 + ch * 16));
            const size_t off = (size_t)row * 4096 + kcg * 64 + ch * 8;
            *(uint4*)(sm + dst)         = *(const uint4*)(AB + off);
            *(uint4*)(sm + 16384 + dst) = *(const uint4*)(BB + off);
        }
        __syncthreads();
        #pragma unroll
        for (int s = 0; s < 4; ++s) {
            const u32 cA = ((u32)((2 * s + ((l >> 4) & 1)) ^ (l & 7))) << 4;
            const u32 cB = ((u32)((2 * s + ((l >> 3) & 1)) ^ (l & 7))) << 4;
            u32 a[2][4], bf[4][4];
            #pragma unroll
            for (int mt = 0; mt < 2; ++mt)
                ldm_x4(a[mt], sb + rowA[mt] + cA);
            #pragma unroll
            for (int g = 0; g < 4; ++g)
                ldm_x4(bf[g], sb + 16384 + rowB[g] + cB);
            #pragma unroll
            for (int mt = 0; mt < 2; ++mt)
                #pragma unroll
                for (int g = 0; g < 4; ++g)
                    #pragma unroll
                    for (int hf = 0; hf < 2; ++hf) {
                        float* A4 = acc[mt][g * 2 + hf];
                        mma_a(A4[0], A4[1], A4[2], A4[3],
                              a[mt][0], a[mt][1], a[mt][2], a[mt][3],
                              bf[g][2 * hf], bf[g][2 * hf + 1]);
                    }
        }
        __syncthreads();
    }

    #pragma unroll
    for (int mt = 0; mt < 2; ++mt) {
        const int o = blko * 128 + wm * 32 + mt * 16 + (l >> 2);
        #pragma unroll
        for (int nt = 0; nt < 8; ++nt) {
            const int m = blkm * 128 + wo * 64 + nt * 8 + 2 * (l & 3);
            float* dst = part + ((size_t)zz * CDIM + o) * NKV + m;
            *(float2*)dst = make_float2(acc[mt][nt][0], acc[mt][nt][1]);
            *(float2*)(dst + 8 * NKV) = make_float2(acc[mt][nt][2], acc[mt][nt][3]);
        }
    }
}

// ===================== conv reduce + BN =======================================
__global__ __launch_bounds__(256) void conv_reduce_bn(
    const float* __restrict__ part,
    const float* __restrict__ gam, const float* __restrict__ bet,
    const float* __restrict__ mu,  const float* __restrict__ var,
    float* __restrict__ xr) {
    const int idx = blockIdx.x * 256 + threadIdx.x;
    const int fl = idx * 4;
    const int b = fl >> 18;
    const int o = (fl >> 10) & 255;
    const int m = fl & 1023;
    float4 s = make_float4(0.f, 0.f, 0.f, 0.f);
    #pragma unroll
    for (int ks = 0; ks < 8; ++ks) {
        const float4 p = *(const float4*)&part[((size_t)(ks * 2 + b) * CDIM + o) * NKV + m];
        s.x += p.x; s.y += p.y; s.z += p.z; s.w += p.w;
    }
    const float inv = gam[o] * rsqrtf(var[o] + EPSBN);
    const float mb = mu[o], be = bet[o];
    float4 r = make_float4((s.x - mb) * inv + be, (s.y - mb) * inv + be,
                           (s.z - mb) * inv + be, (s.w - mb) * inv + be);
    *(float4*)&xr[((size_t)(b * CDIM + o)) * NKV + m] = r;
}

// ===================== k GEMM (scalar f32x2, fp16 epilogue) ===================
__global__ __launch_bounds__(256) void gemm_split(
    const float* __restrict__ W, const float* __restrict__ X,
    u16* __restrict__ Out, int Ncol) {
    __shared__ float As[16][64];
    __shared__ float Bs[16][64];
    const int b  = blockIdx.z;
    const float* Xb = X + (size_t)b * CDIM * Ncol;
    const int bm = blockIdx.y * 64;
    const int bn = blockIdx.x * 64;
    const int tid = threadIdx.x;
    const int tm = tid >> 4, tn = tid & 15;

    u64 acc[4][2] = {};
    for (int k0 = 0; k0 < CDIM; k0 += 16) {
        const int ar = tid >> 2, ac = (tid & 3) * 4;
        float4 a4 = *(const float4*)&W[(size_t)(bm + ar) * CDIM + k0 + ac];
        As[ac + 0][ar] = a4.x; As[ac + 1][ar] = a4.y;
        As[ac + 2][ar] = a4.z; As[ac + 3][ar] = a4.w;
        const int br = tid >> 4, bc = (tid & 15) * 4;
        *(float4*)&Bs[br][bc] = *(const float4*)&Xb[(size_t)(k0 + br) * Ncol + bn + bc];
        __syncthreads();
        #pragma unroll
        for (int kk = 0; kk < 16; ++kk) {
            float4 av = *(const float4*)&As[kk][tm * 4];
            ulonglong2 bv = *(const ulonglong2*)&Bs[kk][tn * 4];
            u64 a0 = pack2(av.x, av.x), a1 = pack2(av.y, av.y);
            u64 a2 = pack2(av.z, av.z), a3 = pack2(av.w, av.w);
            acc[0][0] = fma2(a0, bv.x, acc[0][0]); acc[0][1] = fma2(a0, bv.y, acc[0][1]);
            acc[1][0] = fma2(a1, bv.x, acc[1][0]); acc[1][1] = fma2(a1, bv.y, acc[1][1]);
            acc[2][0] = fma2(a2, bv.x, acc[2][0]); acc[2][1] = fma2(a2, bv.y, acc[2][1]);
            acc[3][0] = fma2(a3, bv.x, acc[3][0]); acc[3][1] = fma2(a3, bv.y, acc[3][1]);
        }
        __syncthreads();
    }
    const int o0 = bm + tm * 4;        // 4 consecutive o (same head), multiple of 4
    const int d0 = o0 & 31;
    const int bh = b * NHEADS + (o0 >> 5);
    #pragma unroll
    for (int j = 0; j < 4; ++j) {
        const int col = bn + tn * 4 + j;
        float vs[4];
        #pragma unroll
        for (int i = 0; i < 4; ++i) {
            float2 f = unpack2(acc[i][j >> 1]);
            vs[i] = (j & 1) ? f.y : f.x;
        }
        u16* base = Out + ((size_t)bh * Ncol + col) * 32 + d0;
        *(u64*)base = cvt4h(make_float4(vs[0], vs[1], vs[2], vs[3]));
    }
}

// ---------------- alpha/bias --------------------------------------------------
__global__ __launch_bounds__(256) void alpha_kernel(
    const float* __restrict__ wproj, const float* __restrict__ v,
    const float* __restrict__ gam, const float* __restrict__ bet,
    const float* __restrict__ mu,  const float* __restrict__ var,
    float* __restrict__ alpha, float* __restrict__ bias) {
    const int b = blockIdx.x;
    const int o = threadIdx.x;
    __shared__ float vs[CDIM];
    vs[o] = v[b * CDIM + o];
    __syncthreads();
    float p = 0.f;
    const float* wr = wproj + (size_t)o * CDIM;
    #pragma unroll 8
    for (int c = 0; c < CDIM; ++c) p = fmaf(wr[c], vs[c], p);
    const float inv = gam[o] * rsqrtf(var[o] + EPSBN);
    alpha[b * CDIM + o] = p * inv;
    if (b == 0) bias[o] = bet[o] - mu[o] * inv;
}

// ===================== fp16 mma.sync attention (f16 accum, kv-split) ==========
// grid (seg 8, half 2, bh 16); 256 threads; smem = k 32KB + q 8KB = 40KB.
#define SM_QOFF 32768
#define SM_TOT  40960
#define NTILES  16

__global__ __launch_bounds__(256, 2)
void attn_mma(const u16* __restrict__ qbf, const u16* __restrict__ kbf,
              float* __restrict__ attn) {
    extern __shared__ char smem[];
    const u32 sb  = smem_u32(smem);
    const int tid = threadIdx.x;
    const int wid = tid >> 5, l = tid & 31;
    const int seg  = blockIdx.x;
    const int half = blockIdx.y;
    const int bh   = blockIdx.z;

    // stage this half's k (512 rows x 64B)
    {
        const uint4* ksrc = (const uint4*)(kbf + (size_t)(bh * NKV + half * 512) * 32);
        for (int idx = tid; idx < 512 * 4; idx += 256) {
            const int row = idx >> 2, c = idx & 3;
            const u32 off = (u32)((row >> 1) * 128 + (row & 1) * 64 + c * 16);
            *(uint4*)(smem + sw128(off)) = ksrc[idx];
        }
    }
    __syncthreads();

    const int brow = (l & 7) + ((l & 16) >> 1);
    u32 baddr[2];
    #pragma unroll
    for (int s = 0; s < 2; ++s) {
        const u32 off = (u32)((brow >> 1) * 128 + (brow & 1) * 64
                              + (2 * s + ((l >> 3) & 1)) * 16);
        baddr[s] = sb + sw128(off);
    }
    const int Rr = wid * 16 + (l & 15);
    u32 aaddr[2];
    #pragma unroll
    for (int s = 0; s < 2; ++s) {
        const u32 off = (u32)((Rr >> 1) * 128 + (Rr & 1) * 64 + (2 * s + (l >> 4)) * 16);
        aaddr[s] = sb + SM_QOFF + sw128(off);
    }

    const float scale = 0.17677669529663687f;
    float* ob = attn + ((size_t)(half * 16 + bh)) * NDIM;
    const u32 NEGINF2 = 0xFC00FC00u;   // half2(-inf, -inf)

    for (int t = 0; t < NTILES; ++t) {
        const int n_base = (seg * NTILES + t) * 128;
        {
            const uint4* qsrc = (const uint4*)(qbf + ((size_t)bh * NDIM + n_base) * 32);
            const int row = tid >> 1;
            const int c0 = (tid & 1) * 2;
            #pragma unroll
            for (int j = 0; j < 2; ++j) {
                const int c = c0 + j;
                const u32 off = (u32)((row >> 1) * 128 + (row & 1) * 64 + c * 16);
                *(uint4*)(smem + SM_QOFF + sw128(off)) = qsrc[(size_t)row * 4 + c];
            }
        }
        __syncwarp();

        u32 a[2][4];
        ldm_x4(a[0], aaddr[0]);
        ldm_x4(a[1], aaddr[1]);
        __syncwarp();

        u32 rm0 = NEGINF2, rm1 = NEGINF2;   // packed running max (row r / row r+8)
        #pragma unroll 4
        for (int kv = 0; kv < 32; ++kv) {
            const u32 off = (u32)kv * 1024;
            u32 b0[4], b1[4];
            ldm_x4(b0, baddr[0] + off);
            ldm_x4(b1, baddr[1] + off);
            #pragma unroll
            for (int g = 0; g < 2; ++g) {
                u32 A0, A1, B0, B1;
                mma_h(A0, A1, a[0][0], a[0][1], a[0][2], a[0][3],
                      b0[2 * g], b0[2 * g + 1]);        // d0-15  -> row r / r+8
                mma_h(B0, B1, a[1][0], a[1][1], a[1][2], a[1][3],
                      b1[2 * g], b1[2 * g + 1]);        // d16-31
                rm0 = hmax2u(rm0, hadd2u(A0, B0));
                rm1 = hmax2u(rm1, hadd2u(A1, B1));
            }
        }
        // unpack packed halves -> float max
        __half2 h0 = *reinterpret_cast<__half2*>(&rm0);
        __half2 h1 = *reinterpret_cast<__half2*>(&rm1);
        float rmax[2];
        rmax[0] = fmaxf(__half2float(__low2half(h0)), __half2float(__high2half(h0)));
        rmax[1] = fmaxf(__half2float(__low2half(h1)), __half2float(__high2half(h1)));
        #pragma unroll
        for (int rr = 0; rr < 2; ++rr) {
            float v = rmax[rr];
            v = fmaxf(v, __shfl_xor_sync(0xffffffffu, v, 1));
            v = fmaxf(v, __shfl_xor_sync(0xffffffffu, v, 2));
            rmax[rr] = v;
        }
        if ((l & 3) == 0) {
            const int rbase = n_base + wid * 16;
            ob[rbase + (l >> 2) + 0] = rmax[0] * scale;
            ob[rbase + (l >> 2) + 8] = rmax[1] * scale;
        }
        __syncwarp();
    }
}

// ---------------- S[b][n] = sum_h max(half0, half1) ---------------------------
__global__ __launch_bounds__(256) void reduce_attn(const float* __restrict__ attn,
                                                   float* __restrict__ S) {
    const int idx = blockIdx.x * 256 + threadIdx.x;
    const int b = idx >> 14, n = idx & (NDIM - 1);
    float s = 0.f;
    #pragma unroll
    for (int h = 0; h < NHEADS; ++h) {
        const size_t base = ((size_t)(b * NHEADS + h)) * NDIM + n;
        s += fmaxf(attn[base], attn[base + (size_t)16 * NDIM]);
    }
    S[idx] = s;
}

// ---------------- out = alpha*S + bias -----------------------------------------
__global__ __launch_bounds__(256) void final_kernel(
    const float* __restrict__ S, const float* __restrict__ alpha,
    const float* __restrict__ bias, float* __restrict__ out) {
    const size_t t = (size_t)blockIdx.x * 256 + threadIdx.x;
    const size_t idx4 = t * 4;
    const int bo = (int)(idx4 >> 14);
    const int n  = (int)(idx4 & (NDIM - 1));
    const int b  = bo >> 8, o = bo & 255;
    const float a  = alpha[bo];
    const float bi = bias[o];
    float4 s = *(const float4*)&S[(size_t)b * NDIM + n];
    float4 r;
    r.x = fmaf(a, s.x, bi); r.y = fmaf(a, s.y, bi);
    r.z = fmaf(a, s.z, bi); r.w = fmaf(a, s.w, bi);
    *(float4*)&out[idx4] = r;
}

// ===================== launch ==================================================
extern "C" void kernel_launch(void* const* d_in, const int* in_sizes, int n_in,
                              void* d_out, int out_size) {
    const float* x      = (const float*)d_in[0];
    const float* w_q    = (const float*)d_in[1];
    const float* w_k    = (const float*)d_in[2];
    const float* w_sr   = (const float*)d_in[3];
    const float* sr_g   = (const float*)d_in[4];
    const float* sr_b   = (const float*)d_in[5];
    const float* sr_m   = (const float*)d_in[6];
    const float* sr_v   = (const float*)d_in[7];
    const float* w_proj = (const float*)d_in[8];
    const float* pj_g   = (const float*)d_in[9];
    const float* pj_b   = (const float*)d_in[10];
    const float* pj_m   = (const float*)d_in[11];
    const float* pj_v   = (const float*)d_in[12];
    float* out = (float*)d_out;

    u16 *qbf, *kbf, *Xt, *Xp, *wqs, *wsrs;
    float *part, *xr, *attn, *S, *vp, *v, *alpha, *bias;
    cudaGetSymbolAddress((void**)&qbf,   g_qbf);
    cudaGetSymbolAddress((void**)&kbf,   g_kbf);
    cudaGetSymbolAddress((void**)&Xt,    g_Xt);
    cudaGetSymbolAddress((void**)&Xp,    g_Xp);
    cudaGetSymbolAddress((void**)&wqs,   g_wqs);
    cudaGetSymbolAddress((void**)&wsrs,  g_wsrs);
    cudaGetSymbolAddress((void**)&part,  g_part);
    cudaGetSymbolAddress((void**)&xr,    g_xr);
    cudaGetSymbolAddress((void**)&attn,  g_attn);
    cudaGetSymbolAddress((void**)&S,     g_S);
    cudaGetSymbolAddress((void**)&vp,    g_vp);
    cudaGetSymbolAddress((void**)&v,     g_v);
    cudaGetSymbolAddress((void**)&alpha, g_alpha);
    cudaGetSymbolAddress((void**)&bias,  g_bias);

    cudaFuncSetAttribute(attn_mma, cudaFuncAttributeMaxDynamicSharedMemorySize, SM_TOT);
    cudaFuncSetAttribute(qgemm_mma, cudaFuncAttributeMaxDynamicSharedMemorySize, 32768);
    cudaFuncSetAttribute(convgemm_mma, cudaFuncAttributeMaxDynamicSharedMemorySize, 32768);
    cudaFuncSetAttribute(gather_patches, cudaFuncAttributeMaxDynamicSharedMemorySize, 32768);

    // prep
    convert_w<<<64, 256>>>(w_q, wqs);
    convert_w<<<1024, 256>>>(w_sr, wsrs);
    transpose_split_x<<<dim3(256, 4, 2), 256>>>(x, Xt, vp);
    gather_patches<<<dim3(8, 32, 2), 256, 32768>>>(x, Xp);
    // q = w_q @ x  (fp16 tensor cores)
    qgemm_mma<<<dim3(128, 2, 2), 256, 32768>>>(Xt, wqs, qbf);
    // xr = BN(conv_sr(x))  (fp16 tensor cores, split-K)
    convgemm_mma<<<dim3(8, 2, 16), 256, 32768>>>(wsrs, Xp, part);
    conv_reduce_bn<<<512, 256>>>(part, sr_g, sr_b, sr_m, sr_v, xr);
    // k = w_k @ xr (scalar, small)
    gemm_split<<<dim3(NKV / 64, CDIM / 64, BSZ), 256>>>(w_k, xr, kbf, NKV);
    // v, alpha
    vp_reduce<<<BSZ * CDIM, 256>>>(vp, v);
    alpha_kernel<<<BSZ, CDIM>>>(w_proj, v, pj_g, pj_b, pj_m, pj_v, alpha, bias);
    // attention rowmax (fp16 tensor cores, f16 accum)
    attn_mma<<<dim3(8, 2, 16), 256, SM_TOT>>>(qbf, kbf, attn);
    // tail
    reduce_attn<<<BSZ * NDIM / 256, 256>>>(attn, S);
    final_kernel<<<(BSZ * CDIM * NDIM / 4) / 256, 256>>>(S, alpha, bias, out);
}

// round 12
// speedup vs baseline: 1.6151x; 1.2770x over previous
#include <cuda_runtime.h>
#include <cuda_fp16.h>
#include <math.h>
#include <cstdint>

// Problem constants
#define BSZ    2
#define CDIM   256
#define NDIM   16384      // 128*128
#define HDIM   128
#define WDIM   128
#define NKV    1024       // 32*32
#define NHEADS 8
#define HD     32
#define EPSBN  1e-5f
#define KSR    4096       // CDIM*4*4

typedef unsigned long long u64;
typedef unsigned int u32;
typedef unsigned short u16;

// ===================== f32x2 helpers (scalar k GEMM) ==========================
__device__ __forceinline__ u64 pack2(float lo, float hi) {
    u64 r; asm("mov.b64 %0, {%1, %2};" : "=l"(r) : "f"(lo), "f"(hi)); return r;
}
__device__ __forceinline__ u64 fma2(u64 a, u64 b, u64 c) {
    u64 d; asm("fma.rn.f32x2 %0, %1, %2, %3;" : "=l"(d) : "l"(a), "l"(b), "l"(c)); return d;
}
__device__ __forceinline__ float2 unpack2(u64 a) {
    float lo, hi; asm("mov.b64 {%0, %1}, %2;" : "=f"(lo), "=f"(hi) : "l"(a));
    return make_float2(lo, hi);
}

// ===================== mma/ldmatrix helpers (fp16) ============================
__device__ __forceinline__ u32 smem_u32(const void* p) {
    u32 a; asm("{ .reg .u64 t; cvta.to.shared.u64 t, %1; cvt.u32.u64 %0, t; }"
               : "=r"(a) : "l"(p)); return a;
}
__device__ __forceinline__ void ldm_x4(u32 r[4], u32 addr) {
    asm volatile("ldmatrix.sync.aligned.m8n8.x4.shared.b16 {%0,%1,%2,%3}, [%4];"
                 : "=r"(r[0]), "=r"(r[1]), "=r"(r[2]), "=r"(r[3]) : "r"(addr));
}
__device__ __forceinline__ void mma_a(float& c0, float& c1, float& c2, float& c3,
                                      u32 a0, u32 a1, u32 a2, u32 a3,
                                      u32 b0, u32 b1) {
    asm volatile("mma.sync.aligned.m16n8k16.row.col.f32.f16.f16.f32 "
                 "{%0,%1,%2,%3}, {%4,%5,%6,%7}, {%8,%9}, {%0,%1,%2,%3};"
                 : "+f"(c0), "+f"(c1), "+f"(c2), "+f"(c3)
                 : "r"(a0), "r"(a1), "r"(a2), "r"(a3), "r"(b0), "r"(b1));
}
// fp16-accumulator MMA, zero C: output packed half2 x2
__device__ __forceinline__ void mma_h(u32& d0, u32& d1,
                                      u32 a0, u32 a1, u32 a2, u32 a3,
                                      u32 b0, u32 b1) {
    asm volatile("mma.sync.aligned.m16n8k16.row.col.f16.f16.f16.f16 "
                 "{%0,%1}, {%2,%3,%4,%5}, {%6,%7}, {%8,%8};"
                 : "=r"(d0), "=r"(d1)
                 : "r"(a0), "r"(a1), "r"(a2), "r"(a3), "r"(b0), "r"(b1), "r"(0u));
}
__device__ __forceinline__ u32 hadd2u(u32 a, u32 b) {
    u32 d; asm("add.f16x2 %0, %1, %2;" : "=r"(d) : "r"(a), "r"(b)); return d;
}
__device__ __forceinline__ u32 hmax2u(u32 a, u32 b) {
    u32 d; asm("max.f16x2 %0, %1, %2;" : "=r"(d) : "r"(a), "r"(b)); return d;
}
__device__ __forceinline__ u32 sw128(u32 b) { return b ^ ((b >> 3) & 0x70); }

// ===================== fp16 pack helpers ======================================
__device__ __forceinline__ u32 cvt2h(float a, float b) {
    __half2 h = __floats2half2_rn(a, b);
    return *reinterpret_cast<u32*>(&h);
}
__device__ __forceinline__ u64 cvt4h(float4 v) {
    u32 lo = cvt2h(v.x, v.y), hi = cvt2h(v.z, v.w);
    return (u64)lo | ((u64)hi << 32);
}

// ===================== scratch ================================================
__device__ __align__(16) u16  g_qbf [BSZ * NHEADS * NDIM * 32];  // fp16, 64B rows
__device__ __align__(16) u16  g_kbf [BSZ * NHEADS * NKV  * 32];  // fp16, 64B rows
__device__ __align__(16) u16  g_Xt  [BSZ * NDIM * 256];          // fp16 single
__device__ __align__(16) u16  g_Xp  [BSZ * NKV * 4096];          // fp16 single
__device__ __align__(16) u16  g_wqs [CDIM * 256];                // fp16 single
__device__ __align__(16) u16  g_wsrs[CDIM * 4096];               // fp16 single
__device__ float g_part[16 * CDIM * NKV];
__device__ float g_xr  [BSZ * CDIM * NKV];
__device__ float g_attn[2 * BSZ * NHEADS * NDIM];                // [half][bh][n]
__device__ float g_S   [BSZ * NDIM];
__device__ float g_vp  [BSZ * CDIM * 256];
__device__ float g_v   [BSZ * CDIM];
__device__ float g_alpha[BSZ * CDIM];
__device__ float g_bias [CDIM];

// ===================== prep: W fp32 -> fp16 rows ==============================
__global__ __launch_bounds__(256) void convert_w(
    const float* __restrict__ W, u16* __restrict__ out) {
    const int idx = blockIdx.x * 256 + threadIdx.x;
    const int fl = idx * 4;
    float4 v = *(const float4*)&W[fl];
    *(u64*)(out + fl) = cvt4h(v);
}

// ===================== prep: x -> Xt (tile transpose -> fp16) + v partials ====
__global__ __launch_bounds__(256) void transpose_split_x(
    const float* __restrict__ x, u16* __restrict__ Xt, float* __restrict__ vp) {
    __shared__ float s[64][65];
    const int n0 = blockIdx.x * 64;
    const int c0 = blockIdx.y * 64;
    const int b  = blockIdx.z;
    const int tid = threadIdx.x;
    #pragma unroll
    for (int i = 0; i < 4; ++i) {
        const int idx = i * 256 + tid;
        const int c_l = idx >> 4, nq = idx & 15;
        float4 v = *(const float4*)&x[((size_t)(b * CDIM + c0 + c_l)) * NDIM + n0 + nq * 4];
        s[c_l][nq * 4 + 0] = v.x; s[c_l][nq * 4 + 1] = v.y;
        s[c_l][nq * 4 + 2] = v.z; s[c_l][nq * 4 + 3] = v.w;
    }
    __syncthreads();
    const int n_l = tid >> 2, cq = tid & 3;
    u16* orow = Xt + ((size_t)(b * NDIM + n0 + n_l)) * 256 + c0;
    #pragma unroll
    for (int i = 0; i < 4; ++i) {
        const int c_loc = (cq + i * 4) * 4;
        float4 v = make_float4(s[c_loc][n_l], s[c_loc + 1][n_l],
                               s[c_loc + 2][n_l], s[c_loc + 3][n_l]);
        *(u64*)(orow + c_loc) = cvt4h(v);
    }
    if (tid < 64) {
        float acc = 0.f;
        #pragma unroll 16
        for (int n = 0; n < 64; ++n) acc += s[tid][n];
        vp[((size_t)(b * CDIM + c0 + tid)) * 256 + blockIdx.x] = acc;
    }
}

// ---------------- v = mean (reduce partials) ----------------------------------
__global__ __launch_bounds__(256) void vp_reduce(const float* __restrict__ vp,
                                                 float* __restrict__ v) {
    const int bc = blockIdx.x;
    __shared__ float red[256];
    red[threadIdx.x] = vp[(size_t)bc * 256 + threadIdx.x];
    __syncthreads();
    for (int st = 128; st > 0; st >>= 1) {
        if (threadIdx.x < st) red[threadIdx.x] += red[threadIdx.x + st];
        __syncthreads();
    }
    if (threadIdx.x == 0) v[bc] = red[0] * (1.0f / NDIM);
}

// ===================== prep: x -> Xp (patch gather -> fp16) ===================
__global__ __launch_bounds__(256) void gather_patches(
    const float* __restrict__ x, u16* __restrict__ Xp) {
    extern __shared__ char gsm[];   // 32KB
    const int cch = blockIdx.x;
    const int hh  = blockIdx.y;
    const int b   = blockIdx.z;
    const int tid = threadIdx.x;
    #pragma unroll
    for (int i = 0; i < 16; ++i) {
        const int idx = i * 256 + tid;
        const int c_l = idx >> 7;
        const int rem = idx & 127;
        const int p = rem >> 5, w4 = rem & 31;
        float4 v = *(const float4*)&x[((size_t)(b * CDIM + cch * 32 + c_l)) * NDIM
                                      + (hh * 4 + p) * WDIM + w4 * 4];
        const u32 off = (u32)(c_l * 32 + p * 8);
        const u32 phys = (off ^ ((u32)(w4 & 15) << 3)) + (u32)w4 * 1024;
        *(u64*)(gsm + phys) = cvt4h(v);
    }
    __syncthreads();
    #pragma unroll
    for (int i = 0; i < 16; ++i) {
        const int idx = i * 256 + tid;
        const int ww = idx >> 7, j = idx & 127;
        const u32 phys = (((u32)j * 8) ^ ((u32)(ww & 15) << 3)) + (u32)ww * 1024;
        u16* dst = Xp + ((size_t)(b * NKV + hh * 32 + ww)) * 4096 + cch * 512 + j * 4;
        *(u64*)dst = *(const u64*)(gsm + phys);
    }
}

// ===================== q GEMM on mma.sync (X single, W single) ================
__global__ __launch_bounds__(256, 1) void qgemm_mma(
    const u16* __restrict__ Xt, const u16* __restrict__ Wq,
    u16* __restrict__ qbf) {
    extern __shared__ char sm[];
    const u32 sb = smem_u32(sm);
    const int tid = threadIdx.x;
    const int l = tid & 31, wid = tid >> 5;
    const int wm = wid & 3, wo = wid >> 2;
    const int blkn = blockIdx.x, blko = blockIdx.y, bb = blockIdx.z;

    const u16* XtB = Xt + (size_t)(bb * NDIM + blkn * 128) * 256;
    const u16* WqB = Wq + (size_t)(blko * 128) * 256;

    float acc[2][8][4];
    #pragma unroll
    for (int a = 0; a < 2; ++a)
        #pragma unroll
        for (int c = 0; c < 8; ++c)
            #pragma unroll
            for (int d = 0; d < 4; ++d) acc[a][c][d] = 0.f;

    u32 rowA[2], rowB[4];
    #pragma unroll
    for (int mt = 0; mt < 2; ++mt)
        rowA[mt] = (u32)(wm * 32 + mt * 16 + (l & 7) + (l & 8)) * 128;
    #pragma unroll
    for (int g = 0; g < 4; ++g)
        rowB[g] = (u32)(wo * 64 + g * 16 + (l & 7) + ((l & 16) >> 1)) * 128;

    for (int kc = 0; kc < 4; ++kc) {
        for (int i = tid; i < 1024; i += 256) {
            const int row = i >> 3, ch = i & 7;
            const u32 dst = sw128((u32)(row * 128 + ch * 16));
            const size_t off = (size_t)row * 256 + kc * 64 + ch * 8;
            *(uint4*)(sm + dst)         = *(const uint4*)(XtB + off);
            *(uint4*)(sm + 16384 + dst) = *(const uint4*)(WqB + off);
        }
        __syncthreads();
        #pragma unroll
        for (int s = 0; s < 4; ++s) {
            const u32 cA = ((u32)((2 * s + ((l >> 4) & 1)) ^ (l & 7))) << 4;
            const u32 cB = ((u32)((2 * s + ((l >> 3) & 1)) ^ (l & 7))) << 4;
            u32 a[2][4], bf[4][4];
            #pragma unroll
            for (int mt = 0; mt < 2; ++mt)
                ldm_x4(a[mt], sb + rowA[mt] + cA);
            #pragma unroll
            for (int g = 0; g < 4; ++g)
                ldm_x4(bf[g], sb + 16384 + rowB[g] + cB);
            #pragma unroll
            for (int mt = 0; mt < 2; ++mt)
                #pragma unroll
                for (int g = 0; g < 4; ++g)
                    #pragma unroll
                    for (int hf = 0; hf < 2; ++hf) {
                        float* A4 = acc[mt][g * 2 + hf];
                        mma_a(A4[0], A4[1], A4[2], A4[3],
                              a[mt][0], a[mt][1], a[mt][2], a[mt][3],
                              bf[g][2 * hf], bf[g][2 * hf + 1]);
                    }
        }
        __syncthreads();
    }

    // epilogue: single fp16 q rows (32 fp16 = 64B)
    #pragma unroll
    for (int mt = 0; mt < 2; ++mt) {
        const int n0g = blkn * 128 + wm * 32 + mt * 16 + (l >> 2);
        #pragma unroll
        for (int nt = 0; nt < 8; ++nt) {
            const int o = blko * 128 + wo * 64 + nt * 8 + 2 * (l & 3);
            const int bh_ = bb * NHEADS + (o >> 5);
            const int d = o & 31;
            u16* base = qbf + ((size_t)bh_ * NDIM + n0g) * 32 + d;
            *(u32*)base = cvt2h(acc[mt][nt][0], acc[mt][nt][1]);
            *(u32*)(base + 8 * 32) = cvt2h(acc[mt][nt][2], acc[mt][nt][3]);
        }
    }
}

// ===================== conv GEMM on mma.sync (single fp16, split-K=8) =========
__global__ __launch_bounds__(256, 1) void convgemm_mma(
    const u16* __restrict__ Wsr, const u16* __restrict__ Xp,
    float* __restrict__ part) {
    extern __shared__ char sm[];
    const u32 sb = smem_u32(sm);
    const int tid = threadIdx.x;
    const int l = tid & 31, wid = tid >> 5;
    const int wm = wid & 3, wo = wid >> 2;
    const int blkm = blockIdx.x, blko = blockIdx.y;
    const int zz = blockIdx.z;
    const int bb = zz & 1, ks = zz >> 1;

    const u16* AB = Wsr + (size_t)(blko * 128) * 4096;
    const u16* BB = Xp + (size_t)(bb * NKV + blkm * 128) * 4096;

    float acc[2][8][4];
    #pragma unroll
    for (int a = 0; a < 2; ++a)
        #pragma unroll
        for (int c = 0; c < 8; ++c)
            #pragma unroll
            for (int d = 0; d < 4; ++d) acc[a][c][d] = 0.f;

    u32 rowA[2], rowB[4];
    #pragma unroll
    for (int mt = 0; mt < 2; ++mt)
        rowA[mt] = (u32)(wm * 32 + mt * 16 + (l & 7) + (l & 8)) * 128;
    #pragma unroll
    for (int g = 0; g < 4; ++g)
        rowB[g] = (u32)(wo * 64 + g * 16 + (l & 7) + ((l & 16) >> 1)) * 128;

    for (int kcl = 0; kcl < 8; ++kcl) {
        const int kcg = ks * 8 + kcl;
        for (int i = tid; i < 1024; i += 256) {
            const int row = i >> 3, ch = i & 7;
            const u32 dst = sw128((u32)(row * 128 + ch * 16));
            const size_t off = (size_t)row * 4096 + kcg * 64 + ch * 8;
            *(uint4*)(sm + dst)         = *(const uint4*)(AB + off);
            *(uint4*)(sm + 16384 + dst) = *(const uint4*)(BB + off);
        }
        __syncthreads();
        #pragma unroll
        for (int s = 0; s < 4; ++s) {
            const u32 cA = ((u32)((2 * s + ((l >> 4) & 1)) ^ (l & 7))) << 4;
            const u32 cB = ((u32)((2 * s + ((l >> 3) & 1)) ^ (l & 7))) << 4;
            u32 a[2][4], bf[4][4];
            #pragma unroll
            for (int mt = 0; mt < 2; ++mt)
                ldm_x4(a[mt], sb + rowA[mt] + cA);
            #pragma unroll
            for (int g = 0; g < 4; ++g)
                ldm_x4(bf[g], sb + 16384 + rowB[g] + cB);
            #pragma unroll
            for (int mt = 0; mt < 2; ++mt)
                #pragma unroll
                for (int g = 0; g < 4; ++g)
                    #pragma unroll
                    for (int hf = 0; hf < 2; ++hf) {
                        float* A4 = acc[mt][g * 2 + hf];
                        mma_a(A4[0], A4[1], A4[2], A4[3],
                              a[mt][0], a[mt][1], a[mt][2], a[mt][3],
                              bf[g][2 * hf], bf[g][2 * hf + 1]);
                    }
        }
        __syncthreads();
    }

    #pragma unroll
    for (int mt = 0; mt < 2; ++mt) {
        const int o = blko * 128 + wm * 32 + mt * 16 + (l >> 2);
        #pragma unroll
        for (int nt = 0; nt < 8; ++nt) {
            const int m = blkm * 128 + wo * 64 + nt * 8 + 2 * (l & 3);
            float* dst = part + ((size_t)zz * CDIM + o) * NKV + m;
            *(float2*)dst = make_float2(acc[mt][nt][0], acc[mt][nt][1]);
            *(float2*)(dst + 8 * NKV) = make_float2(acc[mt][nt][2], acc[mt][nt][3]);
        }
    }
}

// ===================== conv reduce + BN =======================================
__global__ __launch_bounds__(256) void conv_reduce_bn(
    const float* __restrict__ part,
    const float* __restrict__ gam, const float* __restrict__ bet,
    const float* __restrict__ mu,  const float* __restrict__ var,
    float* __restrict__ xr) {
    const int idx = blockIdx.x * 256 + threadIdx.x;
    const int fl = idx * 4;
    const int b = fl >> 18;
    const int o = (fl >> 10) & 255;
    const int m = fl & 1023;
    float4 s = make_float4(0.f, 0.f, 0.f, 0.f);
    #pragma unroll
    for (int ks = 0; ks < 8; ++ks) {
        const float4 p = *(const float4*)&part[((size_t)(ks * 2 + b) * CDIM + o) * NKV + m];
        s.x += p.x; s.y += p.y; s.z += p.z; s.w += p.w;
    }
    const float inv = gam[o] * rsqrtf(var[o] + EPSBN);
    const float mb = mu[o], be = bet[o];
    float4 r = make_float4((s.x - mb) * inv + be, (s.y - mb) * inv + be,
                           (s.z - mb) * inv + be, (s.w - mb) * inv + be);
    *(float4*)&xr[((size_t)(b * CDIM + o)) * NKV + m] = r;
}

// ===================== k GEMM (scalar f32x2, fp16 epilogue) ===================
__global__ __launch_bounds__(256) void gemm_split(
    const float* __restrict__ W, const float* __restrict__ X,
    u16* __restrict__ Out, int Ncol) {
    __shared__ float As[16][64];
    __shared__ float Bs[16][64];
    const int b  = blockIdx.z;
    const float* Xb = X + (size_t)b * CDIM * Ncol;
    const int bm = blockIdx.y * 64;
    const int bn = blockIdx.x * 64;
    const int tid = threadIdx.x;
    const int tm = tid >> 4, tn = tid & 15;

    u64 acc[4][2] = {};
    for (int k0 = 0; k0 < CDIM; k0 += 16) {
        const int ar = tid >> 2, ac = (tid & 3) * 4;
        float4 a4 = *(const float4*)&W[(size_t)(bm + ar) * CDIM + k0 + ac];
        As[ac + 0][ar] = a4.x; As[ac + 1][ar] = a4.y;
        As[ac + 2][ar] = a4.z; As[ac + 3][ar] = a4.w;
        const int br = tid >> 4, bc = (tid & 15) * 4;
        *(float4*)&Bs[br][bc] = *(const float4*)&Xb[(size_t)(k0 + br) * Ncol + bn + bc];
        __syncthreads();
        #pragma unroll
        for (int kk = 0; kk < 16; ++kk) {
            float4 av = *(const float4*)&As[kk][tm * 4];
            ulonglong2 bv = *(const ulonglong2*)&Bs[kk][tn * 4];
            u64 a0 = pack2(av.x, av.x), a1 = pack2(av.y, av.y);
            u64 a2 = pack2(av.z, av.z), a3 = pack2(av.w, av.w);
            acc[0][0] = fma2(a0, bv.x, acc[0][0]); acc[0][1] = fma2(a0, bv.y, acc[0][1]);
            acc[1][0] = fma2(a1, bv.x, acc[1][0]); acc[1][1] = fma2(a1, bv.y, acc[1][1]);
            acc[2][0] = fma2(a2, bv.x, acc[2][0]); acc[2][1] = fma2(a2, bv.y, acc[2][1]);
            acc[3][0] = fma2(a3, bv.x, acc[3][0]); acc[3][1] = fma2(a3, bv.y, acc[3][1]);
        }
        __syncthreads();
    }
    const int o0 = bm + tm * 4;        // 4 consecutive o (same head), multiple of 4
    const int d0 = o0 & 31;
    const int bh = b * NHEADS + (o0 >> 5);
    #pragma unroll
    for (int j = 0; j < 4; ++j) {
        const int col = bn + tn * 4 + j;
        float vs[4];
        #pragma unroll
        for (int i = 0; i < 4; ++i) {
            float2 f = unpack2(acc[i][j >> 1]);
            vs[i] = (j & 1) ? f.y : f.x;
        }
        u16* base = Out + ((size_t)bh * Ncol + col) * 32 + d0;
        *(u64*)base = cvt4h(make_float4(vs[0], vs[1], vs[2], vs[3]));
    }
}

// ---------------- alpha/bias --------------------------------------------------
__global__ __launch_bounds__(256) void alpha_kernel(
    const float* __restrict__ wproj, const float* __restrict__ v,
    const float* __restrict__ gam, const float* __restrict__ bet,
    const float* __restrict__ mu,  const float* __restrict__ var,
    float* __restrict__ alpha, float* __restrict__ bias) {
    const int b = blockIdx.x;
    const int o = threadIdx.x;
    __shared__ float vs[CDIM];
    vs[o] = v[b * CDIM + o];
    __syncthreads();
    float p = 0.f;
    const float* wr = wproj + (size_t)o * CDIM;
    #pragma unroll 8
    for (int c = 0; c < CDIM; ++c) p = fmaf(wr[c], vs[c], p);
    const float inv = gam[o] * rsqrtf(var[o] + EPSBN);
    alpha[b * CDIM + o] = p * inv;
    if (b == 0) bias[o] = bet[o] - mu[o] * inv;
}

// ===================== fp16 mma.sync attention (f16 accum, kv-split) ==========
// grid (seg 8, half 2, bh 16); 256 threads; smem = k 32KB + q 8KB = 40KB.
#define SM_QOFF 32768
#define SM_TOT  40960
#define NTILES  16

__global__ __launch_bounds__(256, 2)
void attn_mma(const u16* __restrict__ qbf, const u16* __restrict__ kbf,
              float* __restrict__ attn) {
    extern __shared__ char smem[];
    const u32 sb  = smem_u32(smem);
    const int tid = threadIdx.x;
    const int wid = tid >> 5, l = tid & 31;
    const int seg  = blockIdx.x;
    const int half = blockIdx.y;
    const int bh   = blockIdx.z;

    // stage this half's k (512 rows x 64B)
    {
        const uint4* ksrc = (const uint4*)(kbf + (size_t)(bh * NKV + half * 512) * 32);
        for (int idx = tid; idx < 512 * 4; idx += 256) {
            const int row = idx >> 2, c = idx & 3;
            const u32 off = (u32)((row >> 1) * 128 + (row & 1) * 64 + c * 16);
            *(uint4*)(smem + sw128(off)) = ksrc[idx];
        }
    }
    __syncthreads();

    const int brow = (l & 7) + ((l & 16) >> 1);
    u32 baddr[2];
    #pragma unroll
    for (int s = 0; s < 2; ++s) {
        const u32 off = (u32)((brow >> 1) * 128 + (brow & 1) * 64
                              + (2 * s + ((l >> 3) & 1)) * 16);
        baddr[s] = sb + sw128(off);
    }
    const int Rr = wid * 16 + (l & 15);
    u32 aaddr[2];
    #pragma unroll
    for (int s = 0; s < 2; ++s) {
        const u32 off = (u32)((Rr >> 1) * 128 + (Rr & 1) * 64 + (2 * s + (l >> 4)) * 16);
        aaddr[s] = sb + SM_QOFF + sw128(off);
    }

    const float scale = 0.17677669529663687f;
    float* ob = attn + ((size_t)(half * 16 + bh)) * NDIM;
    const u32 NEGINF2 = 0xFC00FC00u;   // half2(-inf, -inf)

    for (int t = 0; t < NTILES; ++t) {
        const int n_base = (seg * NTILES + t) * 128;
        {
            const uint4* qsrc = (const uint4*)(qbf + ((size_t)bh * NDIM + n_base) * 32);
            const int row = tid >> 1;
            const int c0 = (tid & 1) * 2;
            #pragma unroll
            for (int j = 0; j < 2; ++j) {
                const int c = c0 + j;
                const u32 off = (u32)((row >> 1) * 128 + (row & 1) * 64 + c * 16);
                *(uint4*)(smem + SM_QOFF + sw128(off)) = qsrc[(size_t)row * 4 + c];
            }
        }
        __syncwarp();

        u32 a[2][4];
        ldm_x4(a[0], aaddr[0]);
        ldm_x4(a[1], aaddr[1]);
        __syncwarp();

        u32 rm0 = NEGINF2, rm1 = NEGINF2;   // packed running max (row r / row r+8)
        #pragma unroll 4
        for (int kv = 0; kv < 32; ++kv) {
            const u32 off = (u32)kv * 1024;
            u32 b0[4], b1[4];
            ldm_x4(b0, baddr[0] + off);
            ldm_x4(b1, baddr[1] + off);
            #pragma unroll
            for (int g = 0; g < 2; ++g) {
                u32 A0, A1, B0, B1;
                mma_h(A0, A1, a[0][0], a[0][1], a[0][2], a[0][3],
                      b0[2 * g], b0[2 * g + 1]);        // d0-15  -> row r / r+8
                mma_h(B0, B1, a[1][0], a[1][1], a[1][2], a[1][3],
                      b1[2 * g], b1[2 * g + 1]);        // d16-31
                rm0 = hmax2u(rm0, hadd2u(A0, B0));
                rm1 = hmax2u(rm1, hadd2u(A1, B1));
            }
        }
        // unpack packed halves -> float max
        __half2 h0 = *reinterpret_cast<__half2*>(&rm0);
        __half2 h1 = *reinterpret_cast<__half2*>(&rm1);
        float rmax[2];
        rmax[0] = fmaxf(__half2float(__low2half(h0)), __half2float(__high2half(h0)));
        rmax[1] = fmaxf(__half2float(__low2half(h1)), __half2float(__high2half(h1)));
        #pragma unroll
        for (int rr = 0; rr < 2; ++rr) {
            float v = rmax[rr];
            v = fmaxf(v, __shfl_xor_sync(0xffffffffu, v, 1));
            v = fmaxf(v, __shfl_xor_sync(0xffffffffu, v, 2));
            rmax[rr] = v;
        }
        if ((l & 3) == 0) {
            const int rbase = n_base + wid * 16;
            ob[rbase + (l >> 2) + 0] = rmax[0] * scale;
            ob[rbase + (l >> 2) + 8] = rmax[1] * scale;
        }
        __syncwarp();
    }
}

// ---------------- S[b][n] = sum_h max(half0, half1) ---------------------------
__global__ __launch_bounds__(256) void reduce_attn(const float* __restrict__ attn,
                                                   float* __restrict__ S) {
    const int idx = blockIdx.x * 256 + threadIdx.x;
    const int b = idx >> 14, n = idx & (NDIM - 1);
    float s = 0.f;
    #pragma unroll
    for (int h = 0; h < NHEADS; ++h) {
        const size_t base = ((size_t)(b * NHEADS + h)) * NDIM + n;
        s += fmaxf(attn[base], attn[base + (size_t)16 * NDIM]);
    }
    S[idx] = s;
}

// ---------------- out = alpha*S + bias -----------------------------------------
__global__ __launch_bounds__(256) void final_kernel(
    const float* __restrict__ S, const float* __restrict__ alpha,
    const float* __restrict__ bias, float* __restrict__ out) {
    const size_t t = (size_t)blockIdx.x * 256 + threadIdx.x;
    const size_t idx4 = t * 4;
    const int bo = (int)(idx4 >> 14);
    const int n  = (int)(idx4 & (NDIM - 1));
    const int b  = bo >> 8, o = bo & 255;
    const float a  = alpha[bo];
    const float bi = bias[o];
    float4 s = *(const float4*)&S[(size_t)b * NDIM + n];
    float4 r;
    r.x = fmaf(a, s.x, bi); r.y = fmaf(a, s.y, bi);
    r.z = fmaf(a, s.z, bi); r.w = fmaf(a, s.w, bi);
    *(float4*)&out[idx4] = r;
}

// ===================== launch (stream-forked for graph overlap) ================
extern "C" void kernel_launch(void* const* d_in, const int* in_sizes, int n_in,
                              void* d_out, int out_size) {
    const float* x      = (const float*)d_in[0];
    const float* w_q    = (const float*)d_in[1];
    const float* w_k    = (const float*)d_in[2];
    const float* w_sr   = (const float*)d_in[3];
    const float* sr_g   = (const float*)d_in[4];
    const float* sr_b   = (const float*)d_in[5];
    const float* sr_m   = (const float*)d_in[6];
    const float* sr_v   = (const float*)d_in[7];
    const float* w_proj = (const float*)d_in[8];
    const float* pj_g   = (const float*)d_in[9];
    const float* pj_b   = (const float*)d_in[10];
    const float* pj_m   = (const float*)d_in[11];
    const float* pj_v   = (const float*)d_in[12];
    float* out = (float*)d_out;

    u16 *qbf, *kbf, *Xt, *Xp, *wqs, *wsrs;
    float *part, *xr, *attn, *S, *vp, *v, *alpha, *bias;
    cudaGetSymbolAddress((void**)&qbf,   g_qbf);
    cudaGetSymbolAddress((void**)&kbf,   g_kbf);
    cudaGetSymbolAddress((void**)&Xt,    g_Xt);
    cudaGetSymbolAddress((void**)&Xp,    g_Xp);
    cudaGetSymbolAddress((void**)&wqs,   g_wqs);
    cudaGetSymbolAddress((void**)&wsrs,  g_wsrs);
    cudaGetSymbolAddress((void**)&part,  g_part);
    cudaGetSymbolAddress((void**)&xr,    g_xr);
    cudaGetSymbolAddress((void**)&attn,  g_attn);
    cudaGetSymbolAddress((void**)&S,     g_S);
    cudaGetSymbolAddress((void**)&vp,    g_vp);
    cudaGetSymbolAddress((void**)&v,     g_v);
    cudaGetSymbolAddress((void**)&alpha, g_alpha);
    cudaGetSymbolAddress((void**)&bias,  g_bias);

    cudaFuncSetAttribute(attn_mma, cudaFuncAttributeMaxDynamicSharedMemorySize, SM_TOT);
    cudaFuncSetAttribute(qgemm_mma, cudaFuncAttributeMaxDynamicSharedMemorySize, 32768);
    cudaFuncSetAttribute(convgemm_mma, cudaFuncAttributeMaxDynamicSharedMemorySize, 32768);
    cudaFuncSetAttribute(gather_patches, cudaFuncAttributeMaxDynamicSharedMemorySize, 32768);

    // Fork a side stream off the (captured) default stream for the q-chain.
    cudaStream_t s1;
    cudaStreamCreateWithFlags(&s1, cudaStreamNonBlocking);
    cudaEvent_t eFork, eJoin;
    cudaEventCreateWithFlags(&eFork, cudaEventDisableTiming);
    cudaEventCreateWithFlags(&eJoin, cudaEventDisableTiming);

    cudaEventRecord(eFork, 0);
    cudaStreamWaitEvent(s1, eFork, 0);

    // ---- side stream s1: q-chain + v/alpha ----
    convert_w<<<64, 256, 0, s1>>>(w_q, wqs);
    transpose_split_x<<<dim3(256, 4, 2), 256, 0, s1>>>(x, Xt, vp);
    qgemm_mma<<<dim3(128, 2, 2), 256, 32768, s1>>>(Xt, wqs, qbf);
    vp_reduce<<<BSZ * CDIM, 256, 0, s1>>>(vp, v);
    alpha_kernel<<<BSZ, CDIM, 0, s1>>>(w_proj, v, pj_g, pj_b, pj_m, pj_v, alpha, bias);
    cudaEventRecord(eJoin, s1);

    // ---- main stream: kv-chain ----
    convert_w<<<1024, 256>>>(w_sr, wsrs);
    gather_patches<<<dim3(8, 32, 2), 256, 32768>>>(x, Xp);
    convgemm_mma<<<dim3(8, 2, 16), 256, 32768>>>(wsrs, Xp, part);
    conv_reduce_bn<<<512, 256>>>(part, sr_g, sr_b, sr_m, sr_v, xr);
    gemm_split<<<dim3(NKV / 64, CDIM / 64, BSZ), 256>>>(w_k, xr, kbf, NKV);

    // ---- join, then attention + tail on main stream ----
    cudaStreamWaitEvent(0, eJoin, 0);
    attn_mma<<<dim3(8, 2, 16), 256, SM_TOT>>>(qbf, kbf, attn);
    reduce_attn<<<BSZ * NDIM / 256, 256>>>(attn, S);
    final_kernel<<<(BSZ * CDIM * NDIM / 4) / 256, 256>>>(S, alpha, bias, out);
    // (streams/events intentionally not destroyed: destruction during graph
    //  capture is unsafe; the handles are host-side only and leak-free for
    //  the handful of kernel_launch invocations the harness performs.)
}

// round 13
// speedup vs baseline: 1.7675x; 1.0944x over previous
#include <cuda_runtime.h>
#include <cuda_fp16.h>
#include <math.h>
#include <cstdint>

// Problem constants
#define BSZ    2
#define CDIM   256
#define NDIM   16384      // 128*128
#define HDIM   128
#define WDIM   128
#define NKV    1024       // 32*32
#define NHEADS 8
#define HD     32
#define EPSBN  1e-5f
#define KSR    4096       // CDIM*4*4

typedef unsigned long long u64;
typedef unsigned int u32;
typedef unsigned short u16;

// ===================== mma/ldmatrix helpers (fp16) ============================
__device__ __forceinline__ u32 smem_u32(const void* p) {
    u32 a; asm("{ .reg .u64 t; cvta.to.shared.u64 t, %1; cvt.u32.u64 %0, t; }"
               : "=r"(a) : "l"(p)); return a;
}
__device__ __forceinline__ void ldm_x4(u32 r[4], u32 addr) {
    asm volatile("ldmatrix.sync.aligned.m8n8.x4.shared.b16 {%0,%1,%2,%3}, [%4];"
                 : "=r"(r[0]), "=r"(r[1]), "=r"(r[2]), "=r"(r[3]) : "r"(addr));
}
__device__ __forceinline__ void mma_a(float& c0, float& c1, float& c2, float& c3,
                                      u32 a0, u32 a1, u32 a2, u32 a3,
                                      u32 b0, u32 b1) {
    asm volatile("mma.sync.aligned.m16n8k16.row.col.f32.f16.f16.f32 "
                 "{%0,%1,%2,%3}, {%4,%5,%6,%7}, {%8,%9}, {%0,%1,%2,%3};"
                 : "+f"(c0), "+f"(c1), "+f"(c2), "+f"(c3)
                 : "r"(a0), "r"(a1), "r"(a2), "r"(a3), "r"(b0), "r"(b1));
}
// fp16-accumulator MMA, zero C: output packed half2 x2
__device__ __forceinline__ void mma_h(u32& d0, u32& d1,
                                      u32 a0, u32 a1, u32 a2, u32 a3,
                                      u32 b0, u32 b1) {
    asm volatile("mma.sync.aligned.m16n8k16.row.col.f16.f16.f16.f16 "
                 "{%0,%1}, {%2,%3,%4,%5}, {%6,%7}, {%8,%8};"
                 : "=r"(d0), "=r"(d1)
                 : "r"(a0), "r"(a1), "r"(a2), "r"(a3), "r"(b0), "r"(b1), "r"(0u));
}
__device__ __forceinline__ u32 hadd2u(u32 a, u32 b) {
    u32 d; asm("add.f16x2 %0, %1, %2;" : "=r"(d) : "r"(a), "r"(b)); return d;
}
__device__ __forceinline__ u32 hmax2u(u32 a, u32 b) {
    u32 d; asm("max.f16x2 %0, %1, %2;" : "=r"(d) : "r"(a), "r"(b)); return d;
}
__device__ __forceinline__ u32 sw128(u32 b) { return b ^ ((b >> 3) & 0x70); }

// ===================== fp16 pack helpers ======================================
__device__ __forceinline__ u32 cvt2h(float a, float b) {
    __half2 h = __floats2half2_rn(a, b);
    return *reinterpret_cast<u32*>(&h);
}
__device__ __forceinline__ u64 cvt4h(float4 v) {
    u32 lo = cvt2h(v.x, v.y), hi = cvt2h(v.z, v.w);
    return (u64)lo | ((u64)hi << 32);
}

// ===================== scratch ================================================
__device__ __align__(16) u16  g_qbf [BSZ * NHEADS * NDIM * 32];  // fp16, 64B rows
__device__ __align__(16) u16  g_kbf [BSZ * NHEADS * NKV  * 32];  // fp16, 64B rows
__device__ __align__(16) u16  g_Xt  [BSZ * NDIM * 256];          // fp16 [n][c]
__device__ __align__(16) u16  g_xrT [BSZ * NKV * 256];           // fp16 [m][c]
__device__ __align__(16) u16  g_Xp  [BSZ * NKV * 4096];          // fp16 [m][ksr]
__device__ __align__(16) u16  g_wqs [CDIM * 256];                // fp16 rows
__device__ __align__(16) u16  g_wks [CDIM * 256];                // fp16 rows
__device__ __align__(16) u16  g_wsrs[CDIM * 4096];               // fp16 rows
__device__ float g_part[16 * CDIM * NKV];
__device__ float g_attn[2 * BSZ * NHEADS * NDIM];                // [half][bh][n]
__device__ float g_S   [BSZ * NDIM];
__device__ float g_vp  [BSZ * CDIM * 256];
__device__ float g_v   [BSZ * CDIM];
__device__ float g_alpha[BSZ * CDIM];
__device__ float g_bias [CDIM];

// ===================== prep: W fp32 -> fp16 rows ==============================
__global__ __launch_bounds__(256) void convert_w(
    const float* __restrict__ W, u16* __restrict__ out) {
    const int idx = blockIdx.x * 256 + threadIdx.x;
    const int fl = idx * 4;
    float4 v = *(const float4*)&W[fl];
    *(u64*)(out + fl) = cvt4h(v);
}

// ===================== prep: x -> Xt (tile transpose -> fp16) + v partials ====
__global__ __launch_bounds__(256) void transpose_split_x(
    const float* __restrict__ x, u16* __restrict__ Xt, float* __restrict__ vp) {
    __shared__ float s[64][65];
    const int n0 = blockIdx.x * 64;
    const int c0 = blockIdx.y * 64;
    const int b  = blockIdx.z;
    const int tid = threadIdx.x;
    #pragma unroll
    for (int i = 0; i < 4; ++i) {
        const int idx = i * 256 + tid;
        const int c_l = idx >> 4, nq = idx & 15;
        float4 v = *(const float4*)&x[((size_t)(b * CDIM + c0 + c_l)) * NDIM + n0 + nq * 4];
        s[c_l][nq * 4 + 0] = v.x; s[c_l][nq * 4 + 1] = v.y;
        s[c_l][nq * 4 + 2] = v.z; s[c_l][nq * 4 + 3] = v.w;
    }
    __syncthreads();
    const int n_l = tid >> 2, cq = tid & 3;
    u16* orow = Xt + ((size_t)(b * NDIM + n0 + n_l)) * 256 + c0;
    #pragma unroll
    for (int i = 0; i < 4; ++i) {
        const int c_loc = (cq + i * 4) * 4;
        float4 v = make_float4(s[c_loc][n_l], s[c_loc + 1][n_l],
                               s[c_loc + 2][n_l], s[c_loc + 3][n_l]);
        *(u64*)(orow + c_loc) = cvt4h(v);
    }
    if (tid < 64) {
        float acc = 0.f;
        #pragma unroll 16
        for (int n = 0; n < 64; ++n) acc += s[tid][n];
        vp[((size_t)(b * CDIM + c0 + tid)) * 256 + blockIdx.x] = acc;
    }
}

// ---------------- v = mean (reduce partials) ----------------------------------
__global__ __launch_bounds__(256) void vp_reduce(const float* __restrict__ vp,
                                                 float* __restrict__ v) {
    const int bc = blockIdx.x;
    __shared__ float red[256];
    red[threadIdx.x] = vp[(size_t)bc * 256 + threadIdx.x];
    __syncthreads();
    for (int st = 128; st > 0; st >>= 1) {
        if (threadIdx.x < st) red[threadIdx.x] += red[threadIdx.x + st];
        __syncthreads();
    }
    if (threadIdx.x == 0) v[bc] = red[0] * (1.0f / NDIM);
}

// ===================== prep: x -> Xp (patch gather -> fp16) ===================
__global__ __launch_bounds__(256) void gather_patches(
    const float* __restrict__ x, u16* __restrict__ Xp) {
    extern __shared__ char gsm[];   // 32KB
    const int cch = blockIdx.x;
    const int hh  = blockIdx.y;
    const int b   = blockIdx.z;
    const int tid = threadIdx.x;
    #pragma unroll
    for (int i = 0; i < 16; ++i) {
        const int idx = i * 256 + tid;
        const int c_l = idx >> 7;
        const int rem = idx & 127;
        const int p = rem >> 5, w4 = rem & 31;
        float4 v = *(const float4*)&x[((size_t)(b * CDIM + cch * 32 + c_l)) * NDIM
                                      + (hh * 4 + p) * WDIM + w4 * 4];
        const u32 off = (u32)(c_l * 32 + p * 8);
        const u32 phys = (off ^ ((u32)(w4 & 15) << 3)) + (u32)w4 * 1024;
        *(u64*)(gsm + phys) = cvt4h(v);
    }
    __syncthreads();
    #pragma unroll
    for (int i = 0; i < 16; ++i) {
        const int idx = i * 256 + tid;
        const int ww = idx >> 7, j = idx & 127;
        const u32 phys = (((u32)j * 8) ^ ((u32)(ww & 15) << 3)) + (u32)ww * 1024;
        u16* dst = Xp + ((size_t)(b * NKV + hh * 32 + ww)) * 4096 + cch * 512 + j * 4;
        *(u64*)dst = *(const u64*)(gsm + phys);
    }
}

// ===================== generic GEMM on mma.sync (M rows @ [row][256] fp16) ====
// Out[bh][row][d] fp16 = A(rows, K=256) @ W^T; Ncol = number of A rows per batch.
__global__ __launch_bounds__(256, 2) void qgemm_mma(
    const u16* __restrict__ Xt, const u16* __restrict__ Wq,
    u16* __restrict__ qbf, int Ncol) {
    extern __shared__ char sm[];
    const u32 sb = smem_u32(sm);
    const int tid = threadIdx.x;
    const int l = tid & 31, wid = tid >> 5;
    const int wm = wid & 3, wo = wid >> 2;
    const int blkn = blockIdx.x, blko = blockIdx.y, bb = blockIdx.z;

    const u16* XtB = Xt + ((size_t)bb * Ncol + blkn * 128) * 256;
    const u16* WqB = Wq + (size_t)(blko * 128) * 256;

    float acc[2][8][4];
    #pragma unroll
    for (int a = 0; a < 2; ++a)
        #pragma unroll
        for (int c = 0; c < 8; ++c)
            #pragma unroll
            for (int d = 0; d < 4; ++d) acc[a][c][d] = 0.f;

    u32 rowA[2], rowB[4];
    #pragma unroll
    for (int mt = 0; mt < 2; ++mt)
        rowA[mt] = (u32)(wm * 32 + mt * 16 + (l & 7) + (l & 8)) * 128;
    #pragma unroll
    for (int g = 0; g < 4; ++g)
        rowB[g] = (u32)(wo * 64 + g * 16 + (l & 7) + ((l & 16) >> 1)) * 128;

    for (int kc = 0; kc < 4; ++kc) {
        for (int i = tid; i < 1024; i += 256) {
            const int row = i >> 3, ch = i & 7;
            const u32 dst = sw128((u32)(row * 128 + ch * 16));
            const size_t off = (size_t)row * 256 + kc * 64 + ch * 8;
            *(uint4*)(sm + dst)         = *(const uint4*)(XtB + off);
            *(uint4*)(sm + 16384 + dst) = *(const uint4*)(WqB + off);
        }
        __syncthreads();
        #pragma unroll
        for (int s = 0; s < 4; ++s) {
            const u32 cA = ((u32)((2 * s + ((l >> 4) & 1)) ^ (l & 7))) << 4;
            const u32 cB = ((u32)((2 * s + ((l >> 3) & 1)) ^ (l & 7))) << 4;
            u32 a[2][4], bf[4][4];
            #pragma unroll
            for (int mt = 0; mt < 2; ++mt)
                ldm_x4(a[mt], sb + rowA[mt] + cA);
            #pragma unroll
            for (int g = 0; g < 4; ++g)
                ldm_x4(bf[g], sb + 16384 + rowB[g] + cB);
            #pragma unroll
            for (int mt = 0; mt < 2; ++mt)
                #pragma unroll
                for (int g = 0; g < 4; ++g)
                    #pragma unroll
                    for (int hf = 0; hf < 2; ++hf) {
                        float* A4 = acc[mt][g * 2 + hf];
                        mma_a(A4[0], A4[1], A4[2], A4[3],
                              a[mt][0], a[mt][1], a[mt][2], a[mt][3],
                              bf[g][2 * hf], bf[g][2 * hf + 1]);
                    }
        }
        __syncthreads();
    }

    // epilogue: fp16 rows (32 fp16 = 64B per (bh,row))
    #pragma unroll
    for (int mt = 0; mt < 2; ++mt) {
        const int n0g = blkn * 128 + wm * 32 + mt * 16 + (l >> 2);
        #pragma unroll
        for (int nt = 0; nt < 8; ++nt) {
            const int o = blko * 128 + wo * 64 + nt * 8 + 2 * (l & 3);
            const int bh_ = bb * NHEADS + (o >> 5);
            const int d = o & 31;
            u16* base = qbf + ((size_t)bh_ * Ncol + n0g) * 32 + d;
            *(u32*)base = cvt2h(acc[mt][nt][0], acc[mt][nt][1]);
            *(u32*)(base + 8 * 32) = cvt2h(acc[mt][nt][2], acc[mt][nt][3]);
        }
    }
}

// ===================== conv GEMM on mma.sync (single fp16, split-K=8) =========
__global__ __launch_bounds__(256, 2) void convgemm_mma(
    const u16* __restrict__ Wsr, const u16* __restrict__ Xp,
    float* __restrict__ part) {
    extern __shared__ char sm[];
    const u32 sb = smem_u32(sm);
    const int tid = threadIdx.x;
    const int l = tid & 31, wid = tid >> 5;
    const int wm = wid & 3, wo = wid >> 2;
    const int blkm = blockIdx.x, blko = blockIdx.y;
    const int zz = blockIdx.z;
    const int bb = zz & 1, ks = zz >> 1;

    const u16* AB = Wsr + (size_t)(blko * 128) * 4096;
    const u16* BB = Xp + (size_t)(bb * NKV + blkm * 128) * 4096;

    float acc[2][8][4];
    #pragma unroll
    for (int a = 0; a < 2; ++a)
        #pragma unroll
        for (int c = 0; c < 8; ++c)
            #pragma unroll
            for (int d = 0; d < 4; ++d) acc[a][c][d] = 0.f;

    u32 rowA[2], rowB[4];
    #pragma unroll
    for (int mt = 0; mt < 2; ++mt)
        rowA[mt] = (u32)(wm * 32 + mt * 16 + (l & 7) + (l & 8)) * 128;
    #pragma unroll
    for (int g = 0; g < 4; ++g)
        rowB[g] = (u32)(wo * 64 + g * 16 + (l & 7) + ((l & 16) >> 1)) * 128;

    for (int kcl = 0; kcl < 8; ++kcl) {
        const int kcg = ks * 8 + kcl;
        for (int i = tid; i < 1024; i += 256) {
            const int row = i >> 3, ch = i & 7;
            const u32 dst = sw128((u32)(row * 128 + ch * 16));
            const size_t off = (size_t)row * 4096 + kcg * 64 + ch * 8;
            *(uint4*)(sm + dst)         = *(const uint4*)(AB + off);
            *(uint4*)(sm + 16384 + dst) = *(const uint4*)(BB + off);
        }
        __syncthreads();
        #pragma unroll
        for (int s = 0; s < 4; ++s) {
            const u32 cA = ((u32)((2 * s + ((l >> 4) & 1)) ^ (l & 7))) << 4;
            const u32 cB = ((u32)((2 * s + ((l >> 3) & 1)) ^ (l & 7))) << 4;
            u32 a[2][4], bf[4][4];
            #pragma unroll
            for (int mt = 0; mt < 2; ++mt)
                ldm_x4(a[mt], sb + rowA[mt] + cA);
            #pragma unroll
            for (int g = 0; g < 4; ++g)
                ldm_x4(bf[g], sb + 16384 + rowB[g] + cB);
            #pragma unroll
            for (int mt = 0; mt < 2; ++mt)
                #pragma unroll
                for (int g = 0; g < 4; ++g)
                    #pragma unroll
                    for (int hf = 0; hf < 2; ++hf) {
                        float* A4 = acc[mt][g * 2 + hf];
                        mma_a(A4[0], A4[1], A4[2], A4[3],
                              a[mt][0], a[mt][1], a[mt][2], a[mt][3],
                              bf[g][2 * hf], bf[g][2 * hf + 1]);
                    }
        }
        __syncthreads();
    }

    #pragma unroll
    for (int mt = 0; mt < 2; ++mt) {
        const int o = blko * 128 + wm * 32 + mt * 16 + (l >> 2);
        #pragma unroll
        for (int nt = 0; nt < 8; ++nt) {
            const int m = blkm * 128 + wo * 64 + nt * 8 + 2 * (l & 3);
            float* dst = part + ((size_t)zz * CDIM + o) * NKV + m;
            *(float2*)dst = make_float2(acc[mt][nt][0], acc[mt][nt][1]);
            *(float2*)(dst + 8 * NKV) = make_float2(acc[mt][nt][2], acc[mt][nt][3]);
        }
    }
}

// ===================== conv reduce + BN + transpose -> xrT fp16 ===============
// grid (m-tiles 16, o-tiles 4, b 2), 256 threads; tile = 64o x 64m.
__global__ __launch_bounds__(256) void conv_reduce_bn_T(
    const float* __restrict__ part,
    const float* __restrict__ gam, const float* __restrict__ bet,
    const float* __restrict__ mu,  const float* __restrict__ var,
    u16* __restrict__ xrT) {
    __shared__ float s[64][65];
    const int m0 = blockIdx.x * 64;
    const int o0 = blockIdx.y * 64;
    const int b  = blockIdx.z;
    const int tid = threadIdx.x;
    const int o_l0 = tid >> 4, m4 = (tid & 15) * 4;
    #pragma unroll
    for (int i = 0; i < 4; ++i) {
        const int o_l = o_l0 + i * 16;
        const int o = o0 + o_l;
        float4 sum = make_float4(0.f, 0.f, 0.f, 0.f);
        #pragma unroll
        for (int ks = 0; ks < 8; ++ks) {
            const float4 p = *(const float4*)&part[((size_t)(ks * 2 + b) * CDIM + o) * NKV + m0 + m4];
            sum.x += p.x; sum.y += p.y; sum.z += p.z; sum.w += p.w;
        }
        const float inv = gam[o] * rsqrtf(var[o] + EPSBN);
        const float mb = mu[o], be = bet[o];
        s[o_l][m4 + 0] = (sum.x - mb) * inv + be;
        s[o_l][m4 + 1] = (sum.y - mb) * inv + be;
        s[o_l][m4 + 2] = (sum.z - mb) * inv + be;
        s[o_l][m4 + 3] = (sum.w - mb) * inv + be;
    }
    __syncthreads();
    const int m_l = tid >> 2, cq = tid & 3;
    u16* orow = xrT + ((size_t)(b * NKV + m0 + m_l)) * 256 + o0;
    #pragma unroll
    for (int j = 0; j < 4; ++j) {
        const int c0 = (cq + j * 4) * 4;
        float4 v = make_float4(s[c0][m_l], s[c0 + 1][m_l],
                               s[c0 + 2][m_l], s[c0 + 3][m_l]);
        *(u64*)(orow + c0) = cvt4h(v);
    }
}

// ---------------- alpha/bias --------------------------------------------------
__global__ __launch_bounds__(256) void alpha_kernel(
    const float* __restrict__ wproj, const float* __restrict__ v,
    const float* __restrict__ gam, const float* __restrict__ bet,
    const float* __restrict__ mu,  const float* __restrict__ var,
    float* __restrict__ alpha, float* __restrict__ bias) {
    const int b = blockIdx.x;
    const int o = threadIdx.x;
    __shared__ float vs[CDIM];
    vs[o] = v[b * CDIM + o];
    __syncthreads();
    float p = 0.f;
    const float* wr = wproj + (size_t)o * CDIM;
    #pragma unroll 8
    for (int c = 0; c < CDIM; ++c) p = fmaf(wr[c], vs[c], p);
    const float inv = gam[o] * rsqrtf(var[o] + EPSBN);
    alpha[b * CDIM + o] = p * inv;
    if (b == 0) bias[o] = bet[o] - mu[o] * inv;
}

// ===================== fp16 mma.sync attention (f16 accum, kv-split) ==========
#define SM_QOFF 32768
#define SM_TOT  40960
#define NTILES  16

__global__ __launch_bounds__(256, 2)
void attn_mma(const u16* __restrict__ qbf, const u16* __restrict__ kbf,
              float* __restrict__ attn) {
    extern __shared__ char smem[];
    const u32 sb  = smem_u32(smem);
    const int tid = threadIdx.x;
    const int wid = tid >> 5, l = tid & 31;
    const int seg  = blockIdx.x;
    const int half = blockIdx.y;
    const int bh   = blockIdx.z;

    // stage this half's k (512 rows x 64B)
    {
        const uint4* ksrc = (const uint4*)(kbf + (size_t)(bh * NKV + half * 512) * 32);
        for (int idx = tid; idx < 512 * 4; idx += 256) {
            const int row = idx >> 2, c = idx & 3;
            const u32 off = (u32)((row >> 1) * 128 + (row & 1) * 64 + c * 16);
            *(uint4*)(smem + sw128(off)) = ksrc[idx];
        }
    }
    __syncthreads();

    const int brow = (l & 7) + ((l & 16) >> 1);
    u32 baddr[2];
    #pragma unroll
    for (int s = 0; s < 2; ++s) {
        const u32 off = (u32)((brow >> 1) * 128 + (brow & 1) * 64
                              + (2 * s + ((l >> 3) & 1)) * 16);
        baddr[s] = sb + sw128(off);
    }
    const int Rr = wid * 16 + (l & 15);
    u32 aaddr[2];
    #pragma unroll
    for (int s = 0; s < 2; ++s) {
        const u32 off = (u32)((Rr >> 1) * 128 + (Rr & 1) * 64 + (2 * s + (l >> 4)) * 16);
        aaddr[s] = sb + SM_QOFF + sw128(off);
    }

    const float scale = 0.17677669529663687f;
    float* ob = attn + ((size_t)(half * 16 + bh)) * NDIM;
    const u32 NEGINF2 = 0xFC00FC00u;   // half2(-inf, -inf)

    for (int t = 0; t < NTILES; ++t) {
        const int n_base = (seg * NTILES + t) * 128;
        {
            const uint4* qsrc = (const uint4*)(qbf + ((size_t)bh * NDIM + n_base) * 32);
            const int row = tid >> 1;
            const int c0 = (tid & 1) * 2;
            #pragma unroll
            for (int j = 0; j < 2; ++j) {
                const int c = c0 + j;
                const u32 off = (u32)((row >> 1) * 128 + (row & 1) * 64 + c * 16);
                *(uint4*)(smem + SM_QOFF + sw128(off)) = qsrc[(size_t)row * 4 + c];
            }
        }
        __syncwarp();

        u32 a[2][4];
        ldm_x4(a[0], aaddr[0]);
        ldm_x4(a[1], aaddr[1]);
        __syncwarp();

        u32 rm0 = NEGINF2, rm1 = NEGINF2;   // packed running max (row r / row r+8)
        #pragma unroll 4
        for (int kv = 0; kv < 32; ++kv) {
            const u32 off = (u32)kv * 1024;
            u32 b0[4], b1[4];
            ldm_x4(b0, baddr[0] + off);
            ldm_x4(b1, baddr[1] + off);
            #pragma unroll
            for (int g = 0; g < 2; ++g) {
                u32 A0, A1, B0, B1;
                mma_h(A0, A1, a[0][0], a[0][1], a[0][2], a[0][3],
                      b0[2 * g], b0[2 * g + 1]);        // d0-15
                mma_h(B0, B1, a[1][0], a[1][1], a[1][2], a[1][3],
                      b1[2 * g], b1[2 * g + 1]);        // d16-31
                rm0 = hmax2u(rm0, hadd2u(A0, B0));
                rm1 = hmax2u(rm1, hadd2u(A1, B1));
            }
        }
        __half2 h0 = *reinterpret_cast<__half2*>(&rm0);
        __half2 h1 = *reinterpret_cast<__half2*>(&rm1);
        float rmax[2];
        rmax[0] = fmaxf(__half2float(__low2half(h0)), __half2float(__high2half(h0)));
        rmax[1] = fmaxf(__half2float(__low2half(h1)), __half2float(__high2half(h1)));
        #pragma unroll
        for (int rr = 0; rr < 2; ++rr) {
            float v = rmax[rr];
            v = fmaxf(v, __shfl_xor_sync(0xffffffffu, v, 1));
            v = fmaxf(v, __shfl_xor_sync(0xffffffffu, v, 2));
            rmax[rr] = v;
        }
        if ((l & 3) == 0) {
            const int rbase = n_base + wid * 16;
            ob[rbase + (l >> 2) + 0] = rmax[0] * scale;
            ob[rbase + (l >> 2) + 8] = rmax[1] * scale;
        }
        __syncwarp();
    }
}

// ---------------- S[b][n] = sum_h max(half0, half1) ---------------------------
__global__ __launch_bounds__(256) void reduce_attn(const float* __restrict__ attn,
                                                   float* __restrict__ S) {
    const int idx = blockIdx.x * 256 + threadIdx.x;
    const int b = idx >> 14, n = idx & (NDIM - 1);
    float s = 0.f;
    #pragma unroll
    for (int h = 0; h < NHEADS; ++h) {
        const size_t base = ((size_t)(b * NHEADS + h)) * NDIM + n;
        s += fmaxf(attn[base], attn[base + (size_t)16 * NDIM]);
    }
    S[idx] = s;
}

// ---------------- out = alpha*S + bias -----------------------------------------
__global__ __launch_bounds__(256) void final_kernel(
    const float* __restrict__ S, const float* __restrict__ alpha,
    const float* __restrict__ bias, float* __restrict__ out) {
    const size_t t = (size_t)blockIdx.x * 256 + threadIdx.x;
    const size_t idx4 = t * 4;
    const int bo = (int)(idx4 >> 14);
    const int n  = (int)(idx4 & (NDIM - 1));
    const int b  = bo >> 8, o = bo & 255;
    const float a  = alpha[bo];
    const float bi = bias[o];
    float4 s = *(const float4*)&S[(size_t)b * NDIM + n];
    float4 r;
    r.x = fmaf(a, s.x, bi); r.y = fmaf(a, s.y, bi);
    r.z = fmaf(a, s.z, bi); r.w = fmaf(a, s.w, bi);
    *(float4*)&out[idx4] = r;
}

// ===================== launch (stream-forked for graph overlap) ================
extern "C" void kernel_launch(void* const* d_in, const int* in_sizes, int n_in,
                              void* d_out, int out_size) {
    const float* x      = (const float*)d_in[0];
    const float* w_q    = (const float*)d_in[1];
    const float* w_k    = (const float*)d_in[2];
    const float* w_sr   = (const float*)d_in[3];
    const float* sr_g   = (const float*)d_in[4];
    const float* sr_b   = (const float*)d_in[5];
    const float* sr_m   = (const float*)d_in[6];
    const float* sr_v   = (const float*)d_in[7];
    const float* w_proj = (const float*)d_in[8];
    const float* pj_g   = (const float*)d_in[9];
    const float* pj_b   = (const float*)d_in[10];
    const float* pj_m   = (const float*)d_in[11];
    const float* pj_v   = (const float*)d_in[12];
    float* out = (float*)d_out;

    u16 *qbf, *kbf, *Xt, *xrT, *Xp, *wqs, *wks, *wsrs;
    float *part, *attn, *S, *vp, *v, *alpha, *bias;
    cudaGetSymbolAddress((void**)&qbf,   g_qbf);
    cudaGetSymbolAddress((void**)&kbf,   g_kbf);
    cudaGetSymbolAddress((void**)&Xt,    g_Xt);
    cudaGetSymbolAddress((void**)&xrT,   g_xrT);
    cudaGetSymbolAddress((void**)&Xp,    g_Xp);
    cudaGetSymbolAddress((void**)&wqs,   g_wqs);
    cudaGetSymbolAddress((void**)&wks,   g_wks);
    cudaGetSymbolAddress((void**)&wsrs,  g_wsrs);
    cudaGetSymbolAddress((void**)&part,  g_part);
    cudaGetSymbolAddress((void**)&attn,  g_attn);
    cudaGetSymbolAddress((void**)&S,     g_S);
    cudaGetSymbolAddress((void**)&vp,    g_vp);
    cudaGetSymbolAddress((void**)&v,     g_v);
    cudaGetSymbolAddress((void**)&alpha, g_alpha);
    cudaGetSymbolAddress((void**)&bias,  g_bias);

    cudaFuncSetAttribute(attn_mma, cudaFuncAttributeMaxDynamicSharedMemorySize, SM_TOT);
    cudaFuncSetAttribute(qgemm_mma, cudaFuncAttributeMaxDynamicSharedMemorySize, 32768);
    cudaFuncSetAttribute(convgemm_mma, cudaFuncAttributeMaxDynamicSharedMemorySize, 32768);
    cudaFuncSetAttribute(gather_patches, cudaFuncAttributeMaxDynamicSharedMemorySize, 32768);

    // Fork a side stream off the (captured) default stream for the q-chain.
    cudaStream_t s1;
    cudaStreamCreateWithFlags(&s1, cudaStreamNonBlocking);
    cudaEvent_t eFork, eJoin;
    cudaEventCreateWithFlags(&eFork, cudaEventDisableTiming);
    cudaEventCreateWithFlags(&eJoin, cudaEventDisableTiming);

    cudaEventRecord(eFork, 0);
    cudaStreamWaitEvent(s1, eFork, 0);

    // ---- side stream s1: q-chain + v/alpha ----
    convert_w<<<64, 256, 0, s1>>>(w_q, wqs);
    transpose_split_x<<<dim3(256, 4, 2), 256, 0, s1>>>(x, Xt, vp);
    qgemm_mma<<<dim3(128, 2, 2), 256, 32768, s1>>>(Xt, wqs, qbf, NDIM);
    vp_reduce<<<BSZ * CDIM, 256, 0, s1>>>(vp, v);
    alpha_kernel<<<BSZ, CDIM, 0, s1>>>(w_proj, v, pj_g, pj_b, pj_m, pj_v, alpha, bias);
    cudaEventRecord(eJoin, s1);

    // ---- main stream: kv-chain ----
    convert_w<<<1024, 256>>>(w_sr, wsrs);
    convert_w<<<64, 256>>>(w_k, wks);
    gather_patches<<<dim3(8, 32, 2), 256, 32768>>>(x, Xp);
    convgemm_mma<<<dim3(8, 2, 16), 256, 32768>>>(wsrs, Xp, part);
    conv_reduce_bn_T<<<dim3(16, 4, 2), 256>>>(part, sr_g, sr_b, sr_m, sr_v, xrT);
    qgemm_mma<<<dim3(8, 2, 2), 256, 32768>>>(xrT, wks, kbf, NKV);   // k GEMM

    // ---- join, then attention + tail on main stream ----
    cudaStreamWaitEvent(0, eJoin, 0);
    attn_mma<<<dim3(8, 2, 16), 256, SM_TOT>>>(qbf, kbf, attn);
    reduce_attn<<<BSZ * NDIM / 256, 256>>>(attn, S);
    final_kernel<<<(BSZ * CDIM * NDIM / 4) / 256, 256>>>(S, alpha, bias, out);
    // (streams/events intentionally not destroyed: destruction during graph
    //  capture is unsafe; host-side handles only.)
}

// round 14
// speedup vs baseline: 1.9288x; 1.0912x over previous
#include <cuda_runtime.h>
#include <cuda_fp16.h>
#include <math.h>
#include <cstdint>

// Problem constants
#define BSZ    2
#define CDIM   256
#define NDIM   16384      // 128*128
#define HDIM   128
#define WDIM   128
#define NKV    1024       // 32*32
#define NHEADS 8
#define HD     32
#define EPSBN  1e-5f
#define KSR    4096       // CDIM*4*4

typedef unsigned long long u64;
typedef unsigned int u32;
typedef unsigned short u16;

// ===================== mma/ldmatrix helpers (fp16) ============================
__device__ __forceinline__ u32 smem_u32(const void* p) {
    u32 a; asm("{ .reg .u64 t; cvta.to.shared.u64 t, %1; cvt.u32.u64 %0, t; }"
               : "=r"(a) : "l"(p)); return a;
}
__device__ __forceinline__ void ldm_x4(u32 r[4], u32 addr) {
    asm volatile("ldmatrix.sync.aligned.m8n8.x4.shared.b16 {%0,%1,%2,%3}, [%4];"
                 : "=r"(r[0]), "=r"(r[1]), "=r"(r[2]), "=r"(r[3]) : "r"(addr));
}
__device__ __forceinline__ void mma_a(float& c0, float& c1, float& c2, float& c3,
                                      u32 a0, u32 a1, u32 a2, u32 a3,
                                      u32 b0, u32 b1) {
    asm volatile("mma.sync.aligned.m16n8k16.row.col.f32.f16.f16.f32 "
                 "{%0,%1,%2,%3}, {%4,%5,%6,%7}, {%8,%9}, {%0,%1,%2,%3};"
                 : "+f"(c0), "+f"(c1), "+f"(c2), "+f"(c3)
                 : "r"(a0), "r"(a1), "r"(a2), "r"(a3), "r"(b0), "r"(b1));
}
// fp16-accumulator MMA, zero C: output packed half2 x2
__device__ __forceinline__ void mma_h(u32& d0, u32& d1,
                                      u32 a0, u32 a1, u32 a2, u32 a3,
                                      u32 b0, u32 b1) {
    asm volatile("mma.sync.aligned.m16n8k16.row.col.f16.f16.f16.f16 "
                 "{%0,%1}, {%2,%3,%4,%5}, {%6,%7}, {%8,%8};"
                 : "=r"(d0), "=r"(d1)
                 : "r"(a0), "r"(a1), "r"(a2), "r"(a3), "r"(b0), "r"(b1), "r"(0u));
}
__device__ __forceinline__ u32 hadd2u(u32 a, u32 b) {
    u32 d; asm("add.f16x2 %0, %1, %2;" : "=r"(d) : "r"(a), "r"(b)); return d;
}
__device__ __forceinline__ u32 hmax2u(u32 a, u32 b) {
    u32 d; asm("max.f16x2 %0, %1, %2;" : "=r"(d) : "r"(a), "r"(b)); return d;
}
__device__ __forceinline__ u32 sw128(u32 b) { return b ^ ((b >> 3) & 0x70); }

// ===================== fp16 pack helpers ======================================
__device__ __forceinline__ u32 cvt2h(float a, float b) {
    __half2 h = __floats2half2_rn(a, b);
    return *reinterpret_cast<u32*>(&h);
}
__device__ __forceinline__ u64 cvt4h(float4 v) {
    u32 lo = cvt2h(v.x, v.y), hi = cvt2h(v.z, v.w);
    return (u64)lo | ((u64)hi << 32);
}

// ===================== scratch ================================================
__device__ __align__(16) u16  g_qbf [BSZ * NHEADS * NDIM * 32];  // fp16, 64B rows
__device__ __align__(16) u16  g_kbf [BSZ * NHEADS * NKV  * 32];  // fp16, 64B rows
__device__ __align__(16) u16  g_Xt  [BSZ * NDIM * 256];          // fp16 [n][c]
__device__ __align__(16) u16  g_xrT [BSZ * NKV * 256];           // fp16 [m][c]
__device__ __align__(16) u16  g_wqs [CDIM * 256];                // fp16 rows
__device__ __align__(16) u16  g_wks [CDIM * 256];                // fp16 rows
__device__ __align__(16) u16  g_wsrs[CDIM * 4096];               // fp16 [o][(pq)*256+c]
__device__ float g_part[16 * CDIM * NKV];
__device__ float g_attn[2 * BSZ * NHEADS * NDIM];                // [half][bh][n]
__device__ float g_S   [BSZ * NDIM];
__device__ float g_vp  [BSZ * CDIM * 256];
__device__ float g_v   [BSZ * CDIM];
__device__ float g_alpha[BSZ * CDIM];
__device__ float g_bias [CDIM];

// ===================== prep: W fp32 -> fp16 rows ==============================
__global__ __launch_bounds__(256) void convert_w(
    const float* __restrict__ W, u16* __restrict__ out) {
    const int idx = blockIdx.x * 256 + threadIdx.x;
    const int fl = idx * 4;
    float4 v = *(const float4*)&W[fl];
    *(u64*)(out + fl) = cvt4h(v);
}

// ===================== prep: w_sr [o][c][p][q] -> fp16 [o][(p4+q)*256+c] ======
__global__ __launch_bounds__(256) void convert_wsr_perm(
    const float* __restrict__ W, u16* __restrict__ out) {
    __shared__ float s[4096];
    const int o = blockIdx.x;
    const int t = threadIdx.x;
    const float* src = W + (size_t)o * 4096;
    #pragma unroll
    for (int j = 0; j < 4; ++j) {
        float4 v = *(const float4*)&src[t * 16 + j * 4];
        s[t * 16 + j * 4 + 0] = v.x; s[t * 16 + j * 4 + 1] = v.y;
        s[t * 16 + j * 4 + 2] = v.z; s[t * 16 + j * 4 + 3] = v.w;
    }
    __syncthreads();
    // thread t: pq = t>>4, c-group cg = t&15 -> writes out[pq*256 + cg*16 .. +15]
    const int pq = t >> 4, cg = t & 15;
    u16* dst = out + (size_t)o * 4096 + pq * 256 + cg * 16;
    #pragma unroll
    for (int j = 0; j < 4; ++j) {
        const int c0 = cg * 16 + j * 4;
        float4 v = make_float4(s[(c0 + 0) * 16 + pq], s[(c0 + 1) * 16 + pq],
                               s[(c0 + 2) * 16 + pq], s[(c0 + 3) * 16 + pq]);
        *(u64*)(dst + j * 4) = cvt4h(v);
    }
}

// ===================== prep: x -> Xt (tile transpose -> fp16) + v partials ====
__global__ __launch_bounds__(256) void transpose_split_x(
    const float* __restrict__ x, u16* __restrict__ Xt, float* __restrict__ vp) {
    __shared__ float s[64][65];
    const int n0 = blockIdx.x * 64;
    const int c0 = blockIdx.y * 64;
    const int b  = blockIdx.z;
    const int tid = threadIdx.x;
    #pragma unroll
    for (int i = 0; i < 4; ++i) {
        const int idx = i * 256 + tid;
        const int c_l = idx >> 4, nq = idx & 15;
        float4 v = *(const float4*)&x[((size_t)(b * CDIM + c0 + c_l)) * NDIM + n0 + nq * 4];
        s[c_l][nq * 4 + 0] = v.x; s[c_l][nq * 4 + 1] = v.y;
        s[c_l][nq * 4 + 2] = v.z; s[c_l][nq * 4 + 3] = v.w;
    }
    __syncthreads();
    const int n_l = tid >> 2, cq = tid & 3;
    u16* orow = Xt + ((size_t)(b * NDIM + n0 + n_l)) * 256 + c0;
    #pragma unroll
    for (int i = 0; i < 4; ++i) {
        const int c_loc = (cq + i * 4) * 4;
        float4 v = make_float4(s[c_loc][n_l], s[c_loc + 1][n_l],
                               s[c_loc + 2][n_l], s[c_loc + 3][n_l]);
        *(u64*)(orow + c_loc) = cvt4h(v);
    }
    if (tid < 64) {
        float acc = 0.f;
        #pragma unroll 16
        for (int n = 0; n < 64; ++n) acc += s[tid][n];
        vp[((size_t)(b * CDIM + c0 + tid)) * 256 + blockIdx.x] = acc;
    }
}

// ---------------- v = mean (reduce partials) ----------------------------------
__global__ __launch_bounds__(256) void vp_reduce(const float* __restrict__ vp,
                                                 float* __restrict__ v) {
    const int bc = blockIdx.x;
    __shared__ float red[256];
    red[threadIdx.x] = vp[(size_t)bc * 256 + threadIdx.x];
    __syncthreads();
    for (int st = 128; st > 0; st >>= 1) {
        if (threadIdx.x < st) red[threadIdx.x] += red[threadIdx.x + st];
        __syncthreads();
    }
    if (threadIdx.x == 0) v[bc] = red[0] * (1.0f / NDIM);
}

// ===================== generic GEMM on mma.sync (M rows @ [row][256] fp16) ====
__global__ __launch_bounds__(256, 2) void qgemm_mma(
    const u16* __restrict__ Xt, const u16* __restrict__ Wq,
    u16* __restrict__ qbf, int Ncol) {
    extern __shared__ char sm[];
    const u32 sb = smem_u32(sm);
    const int tid = threadIdx.x;
    const int l = tid & 31, wid = tid >> 5;
    const int wm = wid & 3, wo = wid >> 2;
    const int blkn = blockIdx.x, blko = blockIdx.y, bb = blockIdx.z;

    const u16* XtB = Xt + ((size_t)bb * Ncol + blkn * 128) * 256;
    const u16* WqB = Wq + (size_t)(blko * 128) * 256;

    float acc[2][8][4];
    #pragma unroll
    for (int a = 0; a < 2; ++a)
        #pragma unroll
        for (int c = 0; c < 8; ++c)
            #pragma unroll
            for (int d = 0; d < 4; ++d) acc[a][c][d] = 0.f;

    u32 rowA[2], rowB[4];
    #pragma unroll
    for (int mt = 0; mt < 2; ++mt)
        rowA[mt] = (u32)(wm * 32 + mt * 16 + (l & 7) + (l & 8)) * 128;
    #pragma unroll
    for (int g = 0; g < 4; ++g)
        rowB[g] = (u32)(wo * 64 + g * 16 + (l & 7) + ((l & 16) >> 1)) * 128;

    for (int kc = 0; kc < 4; ++kc) {
        for (int i = tid; i < 1024; i += 256) {
            const int row = i >> 3, ch = i & 7;
            const u32 dst = sw128((u32)(row * 128 + ch * 16));
            const size_t off = (size_t)row * 256 + kc * 64 + ch * 8;
            *(uint4*)(sm + dst)         = *(const uint4*)(XtB + off);
            *(uint4*)(sm + 16384 + dst) = *(const uint4*)(WqB + off);
        }
        __syncthreads();
        #pragma unroll
        for (int s = 0; s < 4; ++s) {
            const u32 cA = ((u32)((2 * s + ((l >> 4) & 1)) ^ (l & 7))) << 4;
            const u32 cB = ((u32)((2 * s + ((l >> 3) & 1)) ^ (l & 7))) << 4;
            u32 a[2][4], bf[4][4];
            #pragma unroll
            for (int mt = 0; mt < 2; ++mt)
                ldm_x4(a[mt], sb + rowA[mt] + cA);
            #pragma unroll
            for (int g = 0; g < 4; ++g)
                ldm_x4(bf[g], sb + 16384 + rowB[g] + cB);
            #pragma unroll
            for (int mt = 0; mt < 2; ++mt)
                #pragma unroll
                for (int g = 0; g < 4; ++g)
                    #pragma unroll
                    for (int hf = 0; hf < 2; ++hf) {
                        float* A4 = acc[mt][g * 2 + hf];
                        mma_a(A4[0], A4[1], A4[2], A4[3],
                              a[mt][0], a[mt][1], a[mt][2], a[mt][3],
                              bf[g][2 * hf], bf[g][2 * hf + 1]);
                    }
        }
        __syncthreads();
    }

    #pragma unroll
    for (int mt = 0; mt < 2; ++mt) {
        const int n0g = blkn * 128 + wm * 32 + mt * 16 + (l >> 2);
        #pragma unroll
        for (int nt = 0; nt < 8; ++nt) {
            const int o = blko * 128 + wo * 64 + nt * 8 + 2 * (l & 3);
            const int bh_ = bb * NHEADS + (o >> 5);
            const int d = o & 31;
            u16* base = qbf + ((size_t)bh_ * Ncol + n0g) * 32 + d;
            *(u32*)base = cvt2h(acc[mt][nt][0], acc[mt][nt][1]);
            *(u32*)(base + 8 * 32) = cvt2h(acc[mt][nt][2], acc[mt][nt][3]);
        }
    }
}

// ===================== conv GEMM: B gathered from Xt, K order (p,q,c) =========
__global__ __launch_bounds__(256, 2) void convgemm_mma(
    const u16* __restrict__ Wsr, const u16* __restrict__ Xt,
    float* __restrict__ part) {
    extern __shared__ char sm[];
    const u32 sb = smem_u32(sm);
    const int tid = threadIdx.x;
    const int l = tid & 31, wid = tid >> 5;
    const int wm = wid & 3, wo = wid >> 2;
    const int blkm = blockIdx.x, blko = blockIdx.y;
    const int zz = blockIdx.z;
    const int bb = zz & 1, ks = zz >> 1;

    const u16* AB  = Wsr + (size_t)(blko * 128) * 4096;
    const u16* XtB = Xt + (size_t)bb * NDIM * 256;

    float acc[2][8][4];
    #pragma unroll
    for (int a = 0; a < 2; ++a)
        #pragma unroll
        for (int c = 0; c < 8; ++c)
            #pragma unroll
            for (int d = 0; d < 4; ++d) acc[a][c][d] = 0.f;

    u32 rowA[2], rowB[4];
    #pragma unroll
    for (int mt = 0; mt < 2; ++mt)
        rowA[mt] = (u32)(wm * 32 + mt * 16 + (l & 7) + (l & 8)) * 128;
    #pragma unroll
    for (int g = 0; g < 4; ++g)
        rowB[g] = (u32)(wo * 64 + g * 16 + (l & 7) + ((l & 16) >> 1)) * 128;

    for (int kcl = 0; kcl < 8; ++kcl) {
        const int kcg = ks * 8 + kcl;         // 0..63 K-chunk (64 wide)
        const int sect = kcg >> 2;            // pq section 0..15
        const int p = sect >> 2, qq = sect & 3;
        const int ccol = (kcg & 3) * 64;      // c offset within Xt row
        for (int i = tid; i < 1024; i += 256) {
            const int row = i >> 3, ch = i & 7;
            const u32 dst = sw128((u32)(row * 128 + ch * 16));
            // A: Wsr_perm[o][kcg*64 + ...]
            *(uint4*)(sm + dst) = *(const uint4*)(AB + (size_t)row * 4096 + kcg * 64 + ch * 8);
            // B: Xt row n(m, p, q)
            const int m = blkm * 128 + row;
            const int hh = m >> 5, ww = m & 31;
            const int n = (hh * 4 + p) * WDIM + ww * 4 + qq;
            *(uint4*)(sm + 16384 + dst) = *(const uint4*)(XtB + (size_t)n * 256 + ccol + ch * 8);
        }
        __syncthreads();
        #pragma unroll
        for (int s = 0; s < 4; ++s) {
            const u32 cA = ((u32)((2 * s + ((l >> 4) & 1)) ^ (l & 7))) << 4;
            const u32 cB = ((u32)((2 * s + ((l >> 3) & 1)) ^ (l & 7))) << 4;
            u32 a[2][4], bf[4][4];
            #pragma unroll
            for (int mt = 0; mt < 2; ++mt)
                ldm_x4(a[mt], sb + rowA[mt] + cA);
            #pragma unroll
            for (int g = 0; g < 4; ++g)
                ldm_x4(bf[g], sb + 16384 + rowB[g] + cB);
            #pragma unroll
            for (int mt = 0; mt < 2; ++mt)
                #pragma unroll
                for (int g = 0; g < 4; ++g)
                    #pragma unroll
                    for (int hf = 0; hf < 2; ++hf) {
                        float* A4 = acc[mt][g * 2 + hf];
                        mma_a(A4[0], A4[1], A4[2], A4[3],
                              a[mt][0], a[mt][1], a[mt][2], a[mt][3],
                              bf[g][2 * hf], bf[g][2 * hf + 1]);
                    }
        }
        __syncthreads();
    }

    #pragma unroll
    for (int mt = 0; mt < 2; ++mt) {
        const int o = blko * 128 + wm * 32 + mt * 16 + (l >> 2);
        #pragma unroll
        for (int nt = 0; nt < 8; ++nt) {
            const int m = blkm * 128 + wo * 64 + nt * 8 + 2 * (l & 3);
            float* dst = part + ((size_t)zz * CDIM + o) * NKV + m;
            *(float2*)dst = make_float2(acc[mt][nt][0], acc[mt][nt][1]);
            *(float2*)(dst + 8 * NKV) = make_float2(acc[mt][nt][2], acc[mt][nt][3]);
        }
    }
}

// ===================== conv reduce + BN + transpose -> xrT fp16 ===============
__global__ __launch_bounds__(256) void conv_reduce_bn_T(
    const float* __restrict__ part,
    const float* __restrict__ gam, const float* __restrict__ bet,
    const float* __restrict__ mu,  const float* __restrict__ var,
    u16* __restrict__ xrT) {
    __shared__ float s[64][65];
    const int m0 = blockIdx.x * 64;
    const int o0 = blockIdx.y * 64;
    const int b  = blockIdx.z;
    const int tid = threadIdx.x;
    const int o_l0 = tid >> 4, m4 = (tid & 15) * 4;
    #pragma unroll
    for (int i = 0; i < 4; ++i) {
        const int o_l = o_l0 + i * 16;
        const int o = o0 + o_l;
        float4 sum = make_float4(0.f, 0.f, 0.f, 0.f);
        #pragma unroll
        for (int ks = 0; ks < 8; ++ks) {
            const float4 p = *(const float4*)&part[((size_t)(ks * 2 + b) * CDIM + o) * NKV + m0 + m4];
            sum.x += p.x; sum.y += p.y; sum.z += p.z; sum.w += p.w;
        }
        const float inv = gam[o] * rsqrtf(var[o] + EPSBN);
        const float mb = mu[o], be = bet[o];
        s[o_l][m4 + 0] = (sum.x - mb) * inv + be;
        s[o_l][m4 + 1] = (sum.y - mb) * inv + be;
        s[o_l][m4 + 2] = (sum.z - mb) * inv + be;
        s[o_l][m4 + 3] = (sum.w - mb) * inv + be;
    }
    __syncthreads();
    const int m_l = tid >> 2, cq = tid & 3;
    u16* orow = xrT + ((size_t)(b * NKV + m0 + m_l)) * 256 + o0;
    #pragma unroll
    for (int j = 0; j < 4; ++j) {
        const int c0 = (cq + j * 4) * 4;
        float4 v = make_float4(s[c0][m_l], s[c0 + 1][m_l],
                               s[c0 + 2][m_l], s[c0 + 3][m_l]);
        *(u64*)(orow + c0) = cvt4h(v);
    }
}

// ---------------- alpha/bias --------------------------------------------------
__global__ __launch_bounds__(256) void alpha_kernel(
    const float* __restrict__ wproj, const float* __restrict__ v,
    const float* __restrict__ gam, const float* __restrict__ bet,
    const float* __restrict__ mu,  const float* __restrict__ var,
    float* __restrict__ alpha, float* __restrict__ bias) {
    const int b = blockIdx.x;
    const int o = threadIdx.x;
    __shared__ float vs[CDIM];
    vs[o] = v[b * CDIM + o];
    __syncthreads();
    float p = 0.f;
    const float* wr = wproj + (size_t)o * CDIM;
    #pragma unroll 8
    for (int c = 0; c < CDIM; ++c) p = fmaf(wr[c], vs[c], p);
    const float inv = gam[o] * rsqrtf(var[o] + EPSBN);
    alpha[b * CDIM + o] = p * inv;
    if (b == 0) bias[o] = bet[o] - mu[o] * inv;
}

// ===================== fp16 mma.sync attention (f16 accum, kv-split) ==========
#define SM_QOFF 32768
#define SM_TOT  40960
#define NTILES  16

__global__ __launch_bounds__(256, 2)
void attn_mma(const u16* __restrict__ qbf, const u16* __restrict__ kbf,
              float* __restrict__ attn) {
    extern __shared__ char smem[];
    const u32 sb  = smem_u32(smem);
    const int tid = threadIdx.x;
    const int wid = tid >> 5, l = tid & 31;
    const int seg  = blockIdx.x;
    const int half = blockIdx.y;
    const int bh   = blockIdx.z;

    {
        const uint4* ksrc = (const uint4*)(kbf + (size_t)(bh * NKV + half * 512) * 32);
        for (int idx = tid; idx < 512 * 4; idx += 256) {
            const int row = idx >> 2, c = idx & 3;
            const u32 off = (u32)((row >> 1) * 128 + (row & 1) * 64 + c * 16);
            *(uint4*)(smem + sw128(off)) = ksrc[idx];
        }
    }
    __syncthreads();

    const int brow = (l & 7) + ((l & 16) >> 1);
    u32 baddr[2];
    #pragma unroll
    for (int s = 0; s < 2; ++s) {
        const u32 off = (u32)((brow >> 1) * 128 + (brow & 1) * 64
                              + (2 * s + ((l >> 3) & 1)) * 16);
        baddr[s] = sb + sw128(off);
    }
    const int Rr = wid * 16 + (l & 15);
    u32 aaddr[2];
    #pragma unroll
    for (int s = 0; s < 2; ++s) {
        const u32 off = (u32)((Rr >> 1) * 128 + (Rr & 1) * 64 + (2 * s + (l >> 4)) * 16);
        aaddr[s] = sb + SM_QOFF + sw128(off);
    }

    const float scale = 0.17677669529663687f;
    float* ob = attn + ((size_t)(half * 16 + bh)) * NDIM;
    const u32 NEGINF2 = 0xFC00FC00u;

    for (int t = 0; t < NTILES; ++t) {
        const int n_base = (seg * NTILES + t) * 128;
        {
            const uint4* qsrc = (const uint4*)(qbf + ((size_t)bh * NDIM + n_base) * 32);
            const int row = tid >> 1;
            const int c0 = (tid & 1) * 2;
            #pragma unroll
            for (int j = 0; j < 2; ++j) {
                const int c = c0 + j;
                const u32 off = (u32)((row >> 1) * 128 + (row & 1) * 64 + c * 16);
                *(uint4*)(smem + SM_QOFF + sw128(off)) = qsrc[(size_t)row * 4 + c];
            }
        }
        __syncwarp();

        u32 a[2][4];
        ldm_x4(a[0], aaddr[0]);
        ldm_x4(a[1], aaddr[1]);
        __syncwarp();

        u32 rm0 = NEGINF2, rm1 = NEGINF2;
        #pragma unroll 4
        for (int kv = 0; kv < 32; ++kv) {
            const u32 off = (u32)kv * 1024;
            u32 b0[4], b1[4];
            ldm_x4(b0, baddr[0] + off);
            ldm_x4(b1, baddr[1] + off);
            #pragma unroll
            for (int g = 0; g < 2; ++g) {
                u32 A0, A1, B0, B1;
                mma_h(A0, A1, a[0][0], a[0][1], a[0][2], a[0][3],
                      b0[2 * g], b0[2 * g + 1]);
                mma_h(B0, B1, a[1][0], a[1][1], a[1][2], a[1][3],
                      b1[2 * g], b1[2 * g + 1]);
                rm0 = hmax2u(rm0, hadd2u(A0, B0));
                rm1 = hmax2u(rm1, hadd2u(A1, B1));
            }
        }
        __half2 h0 = *reinterpret_cast<__half2*>(&rm0);
        __half2 h1 = *reinterpret_cast<__half2*>(&rm1);
        float rmax[2];
        rmax[0] = fmaxf(__half2float(__low2half(h0)), __half2float(__high2half(h0)));
        rmax[1] = fmaxf(__half2float(__low2half(h1)), __half2float(__high2half(h1)));
        #pragma unroll
        for (int rr = 0; rr < 2; ++rr) {
            float v = rmax[rr];
            v = fmaxf(v, __shfl_xor_sync(0xffffffffu, v, 1));
            v = fmaxf(v, __shfl_xor_sync(0xffffffffu, v, 2));
            rmax[rr] = v;
        }
        if ((l & 3) == 0) {
            const int rbase = n_base + wid * 16;
            ob[rbase + (l >> 2) + 0] = rmax[0] * scale;
            ob[rbase + (l >> 2) + 8] = rmax[1] * scale;
        }
        __syncwarp();
    }
}

// ---------------- S[b][n] = sum_h max(half0, half1) ---------------------------
__global__ __launch_bounds__(256) void reduce_attn(const float* __restrict__ attn,
                                                   float* __restrict__ S) {
    const int idx = blockIdx.x * 256 + threadIdx.x;
    const int b = idx >> 14, n = idx & (NDIM - 1);
    float s = 0.f;
    #pragma unroll
    for (int h = 0; h < NHEADS; ++h) {
        const size_t base = ((size_t)(b * NHEADS + h)) * NDIM + n;
        s += fmaxf(attn[base], attn[base + (size_t)16 * NDIM]);
    }
    S[idx] = s;
}

// ---------------- out = alpha*S + bias -----------------------------------------
__global__ __launch_bounds__(256) void final_kernel(
    const float* __restrict__ S, const float* __restrict__ alpha,
    const float* __restrict__ bias, float* __restrict__ out) {
    const size_t t = (size_t)blockIdx.x * 256 + threadIdx.x;
    const size_t idx4 = t * 4;
    const int bo = (int)(idx4 >> 14);
    const int n  = (int)(idx4 & (NDIM - 1));
    const int b  = bo >> 8, o = bo & 255;
    const float a  = alpha[bo];
    const float bi = bias[o];
    float4 s = *(const float4*)&S[(size_t)b * NDIM + n];
    float4 r;
    r.x = fmaf(a, s.x, bi); r.y = fmaf(a, s.y, bi);
    r.z = fmaf(a, s.z, bi); r.w = fmaf(a, s.w, bi);
    *(float4*)&out[idx4] = r;
}

// ===================== launch (stream-forked for graph overlap) ================
extern "C" void kernel_launch(void* const* d_in, const int* in_sizes, int n_in,
                              void* d_out, int out_size) {
    const float* x      = (const float*)d_in[0];
    const float* w_q    = (const float*)d_in[1];
    const float* w_k    = (const float*)d_in[2];
    const float* w_sr   = (const float*)d_in[3];
    const float* sr_g   = (const float*)d_in[4];
    const float* sr_b   = (const float*)d_in[5];
    const float* sr_m   = (const float*)d_in[6];
    const float* sr_v   = (const float*)d_in[7];
    const float* w_proj = (const float*)d_in[8];
    const float* pj_g   = (const float*)d_in[9];
    const float* pj_b   = (const float*)d_in[10];
    const float* pj_m   = (const float*)d_in[11];
    const float* pj_v   = (const float*)d_in[12];
    float* out = (float*)d_out;

    u16 *qbf, *kbf, *Xt, *xrT, *wqs, *wks, *wsrs;
    float *part, *attn, *S, *vp, *v, *alpha, *bias;
    cudaGetSymbolAddress((void**)&qbf,   g_qbf);
    cudaGetSymbolAddress((void**)&kbf,   g_kbf);
    cudaGetSymbolAddress((void**)&Xt,    g_Xt);
    cudaGetSymbolAddress((void**)&xrT,   g_xrT);
    cudaGetSymbolAddress((void**)&wqs,   g_wqs);
    cudaGetSymbolAddress((void**)&wks,   g_wks);
    cudaGetSymbolAddress((void**)&wsrs,  g_wsrs);
    cudaGetSymbolAddress((void**)&part,  g_part);
    cudaGetSymbolAddress((void**)&attn,  g_attn);
    cudaGetSymbolAddress((void**)&S,     g_S);
    cudaGetSymbolAddress((void**)&vp,    g_vp);
    cudaGetSymbolAddress((void**)&v,     g_v);
    cudaGetSymbolAddress((void**)&alpha, g_alpha);
    cudaGetSymbolAddress((void**)&bias,  g_bias);

    cudaFuncSetAttribute(attn_mma, cudaFuncAttributeMaxDynamicSharedMemorySize, SM_TOT);
    cudaFuncSetAttribute(qgemm_mma, cudaFuncAttributeMaxDynamicSharedMemorySize, 32768);
    cudaFuncSetAttribute(convgemm_mma, cudaFuncAttributeMaxDynamicSharedMemorySize, 32768);

    cudaStream_t s1;
    cudaStreamCreateWithFlags(&s1, cudaStreamNonBlocking);
    cudaEvent_t eFork, eJoin;
    cudaEventCreateWithFlags(&eFork, cudaEventDisableTiming);
    cudaEventCreateWithFlags(&eJoin, cudaEventDisableTiming);

    // ---- main: weight converts + the single x pass ----
    convert_w<<<64, 256>>>(w_q, wqs);
    convert_w<<<64, 256>>>(w_k, wks);
    convert_wsr_perm<<<256, 256>>>(w_sr, wsrs);
    transpose_split_x<<<dim3(256, 4, 2), 256>>>(x, Xt, vp);

    cudaEventRecord(eFork, 0);
    cudaStreamWaitEvent(s1, eFork, 0);

    // ---- side stream s1: q-chain + v/alpha ----
    qgemm_mma<<<dim3(128, 2, 2), 256, 32768, s1>>>(Xt, wqs, qbf, NDIM);
    vp_reduce<<<BSZ * CDIM, 256, 0, s1>>>(vp, v);
    alpha_kernel<<<BSZ, CDIM, 0, s1>>>(w_proj, v, pj_g, pj_b, pj_m, pj_v, alpha, bias);
    cudaEventRecord(eJoin, s1);

    // ---- main stream: kv-chain (conv B gathered straight from Xt) ----
    convgemm_mma<<<dim3(8, 2, 16), 256, 32768>>>(wsrs, Xt, part);
    conv_reduce_bn_T<<<dim3(16, 4, 2), 256>>>(part, sr_g, sr_b, sr_m, sr_v, xrT);
    qgemm_mma<<<dim3(8, 2, 2), 256, 32768>>>(xrT, wks, kbf, NKV);   // k GEMM

    // ---- join, then attention + tail ----
    cudaStreamWaitEvent(0, eJoin, 0);
    attn_mma<<<dim3(8, 2, 16), 256, SM_TOT>>>(qbf, kbf, attn);
    reduce_attn<<<BSZ * NDIM / 256, 256>>>(attn, S);
    final_kernel<<<(BSZ * CDIM * NDIM / 4) / 256, 256>>>(S, alpha, bias, out);
}